// round 1
// baseline (speedup 1.0000x reference)
#include <cuda_runtime.h>

#define NNODE 50000
#define NEDGE 200000
#define NG    64
#define NF    1536
#define NH    1024
#define NC    80
#define NFUSE 1024
#define NCOMB (NF + NH)   // 2560

// ---------------- scratch (device globals; no allocation allowed) ----------
__device__ float g_buf1[(size_t)NNODE * NH];   // 204.8 MB
__device__ float g_buf2[(size_t)NNODE * NH];   // 204.8 MB
__device__ float g_deg [NNODE];
__device__ float g_dis [NNODE];
__device__ float g_norm[NEDGE];
__device__ float g_pooled[NG * NH];
__device__ float g_cnt [NG];
__device__ float g_comb[NG * NCOMB];
__device__ float g_hid [NG * NFUSE];

// ---------------- degree / normalization ----------------------------------
__global__ void k_deg_init(float* deg) {
    int n = blockIdx.x * blockDim.x + threadIdx.x;
    if (n < NNODE) deg[n] = 1.0f;                 // self-loop
}

__global__ void k_deg_count(const int* __restrict__ dst, float* deg) {
    int e = blockIdx.x * blockDim.x + threadIdx.x;
    if (e < NEDGE) atomicAdd(&deg[dst[e]], 1.0f);
}

__global__ void k_dis(const float* __restrict__ deg, float* dis) {
    int n = blockIdx.x * blockDim.x + threadIdx.x;
    if (n < NNODE) dis[n] = rsqrtf(deg[n]);
}

__global__ void k_norm(const int* __restrict__ src, const int* __restrict__ dst,
                       const float* __restrict__ dis, float* norm) {
    int e = blockIdx.x * blockDim.x + threadIdx.x;
    if (e < NEDGE) norm[e] = dis[src[e]] * dis[dst[e]];
}

// ---------------- SGEMM: C[M,N] = A[M,K] @ B[K,N] --------------------------
// 128x128 block tile, BK=8, 256 threads, 8x8 per-thread register tile.
__global__ __launch_bounds__(256)
void sgemm128(const float* __restrict__ A, const float* __restrict__ B,
              float* __restrict__ C, int M, int N, int K) {
    __shared__ float As[8][128];
    __shared__ float Bs[8][128];

    const int tid = threadIdx.x;
    const int tx = tid & 15;         // 0..15
    const int ty = tid >> 4;         // 0..15
    const int rowBase = blockIdx.y * 128;
    const int colBase = blockIdx.x * 128;

    // A tile load: 128 rows x 8 k, 2 threads/row, float4 along K
    const int arow = tid >> 1;              // 0..127
    const int acol = (tid & 1) * 4;         // 0 or 4
    // B tile load: 8 k-rows x 128 cols, float4 along N
    const int brow = tid >> 5;              // 0..7
    const int bcol = (tid & 31) * 4;

    const int  aRowG  = rowBase + arow;
    const bool aValid = aRowG < M;
    const float* Aptr = A + (size_t)aRowG * K + acol;
    const float* Bptr = B + (size_t)brow * N + colBase + bcol;

    float acc[8][8];
#pragma unroll
    for (int i = 0; i < 8; i++)
#pragma unroll
        for (int j = 0; j < 8; j++) acc[i][j] = 0.0f;

    for (int k0 = 0; k0 < K; k0 += 8) {
        float4 av = aValid ? *(const float4*)(Aptr + k0)
                           : make_float4(0.f, 0.f, 0.f, 0.f);
        float4 bv = *(const float4*)(Bptr + (size_t)k0 * N);

        __syncthreads();            // previous iter's reads done
        As[acol + 0][arow] = av.x;
        As[acol + 1][arow] = av.y;
        As[acol + 2][arow] = av.z;
        As[acol + 3][arow] = av.w;
        *(float4*)&Bs[brow][bcol] = bv;
        __syncthreads();

#pragma unroll
        for (int k = 0; k < 8; k++) {
            float a[8], b[8];
            *(float4*)&a[0] = *(const float4*)&As[k][ty * 8];
            *(float4*)&a[4] = *(const float4*)&As[k][ty * 8 + 4];
            *(float4*)&b[0] = *(const float4*)&Bs[k][tx * 8];
            *(float4*)&b[4] = *(const float4*)&Bs[k][tx * 8 + 4];
#pragma unroll
            for (int i = 0; i < 8; i++)
#pragma unroll
                for (int j = 0; j < 8; j++) acc[i][j] += a[i] * b[j];
        }
    }

#pragma unroll
    for (int i = 0; i < 8; i++) {
        int r = rowBase + ty * 8 + i;
        if (r < M) {
            float* cp = C + (size_t)r * N + colBase + tx * 8;
            *(float4*)(cp)     = make_float4(acc[i][0], acc[i][1], acc[i][2], acc[i][3]);
            *(float4*)(cp + 4) = make_float4(acc[i][4], acc[i][5], acc[i][6], acc[i][7]);
        }
    }
}

// ---------------- message passing ------------------------------------------
// out[n,:] = in[n,:] * dis[n]^2   (self-loop term; also serves as init)
__global__ void k_selfloop(const float* __restrict__ in, const float* __restrict__ dis,
                           float* __restrict__ out) {
    size_t idx = (size_t)blockIdx.x * blockDim.x + threadIdx.x;   // over N*NH/4
    if (idx >= (size_t)NNODE * (NH / 4)) return;
    int n = (int)(idx >> 8);                  // NH/4 == 256
    float s = dis[n] * dis[n];
    float4 v = ((const float4*)in)[idx];
    v.x *= s; v.y *= s; v.z *= s; v.w *= s;
    ((float4*)out)[idx] = v;
}

// one block per edge: out[dst] += in[src] * norm[e]
__global__ __launch_bounds__(256)
void k_scatter(const float* __restrict__ in, float* __restrict__ out,
               const int* __restrict__ src, const int* __restrict__ dst,
               const float* __restrict__ norm) {
    int e = blockIdx.x;
    float w = norm[e];
    const float4* ip = (const float4*)(in + (size_t)src[e] * NH);
    float* op = out + (size_t)dst[e] * NH + threadIdx.x * 4;
    float4 v = ip[threadIdx.x];
    atomicAdd(op + 0, v.x * w);
    atomicAdd(op + 1, v.y * w);
    atomicAdd(op + 2, v.z * w);
    atomicAdd(op + 3, v.w * w);
}

__global__ void k_bias_relu(float* __restrict__ x, const float* __restrict__ b) {
    size_t idx = (size_t)blockIdx.x * blockDim.x + threadIdx.x;   // over N*NH/4
    if (idx >= (size_t)NNODE * (NH / 4)) return;
    int h = ((int)idx & (NH / 4 - 1)) * 4;
    float4 v = ((float4*)x)[idx];
    v.x = fmaxf(v.x + b[h + 0], 0.f);
    v.y = fmaxf(v.y + b[h + 1], 0.f);
    v.z = fmaxf(v.z + b[h + 2], 0.f);
    v.w = fmaxf(v.w + b[h + 3], 0.f);
    ((float4*)x)[idx] = v;
}

// ---------------- pooling + head -------------------------------------------
__global__ void k_zero_pool(float* pooled, float* cnt) {
    int i = blockIdx.x * blockDim.x + threadIdx.x;
    if (i < NG * NH) pooled[i] = 0.f;
    if (i < NG) cnt[i] = 0.f;
}

__global__ void k_count(const int* __restrict__ batch, float* cnt) {
    int n = blockIdx.x * blockDim.x + threadIdx.x;
    if (n < NNODE) atomicAdd(&cnt[batch[n]], 1.0f);
}

__global__ __launch_bounds__(256)
void k_pool(const float* __restrict__ a, const int* __restrict__ batch,
            float* __restrict__ pooled) {
    int n = blockIdx.x;
    int g = batch[n];
    float4 v = ((const float4*)(a + (size_t)n * NH))[threadIdx.x];
    float* op = pooled + (size_t)g * NH + threadIdx.x * 4;
    atomicAdd(op + 0, v.x);
    atomicAdd(op + 1, v.y);
    atomicAdd(op + 2, v.z);
    atomicAdd(op + 3, v.w);
}

__global__ void k_comb(const float* __restrict__ gx, const float* __restrict__ pooled,
                       const float* __restrict__ cnt, float* __restrict__ comb) {
    int g = blockIdx.y;
    int i = blockIdx.x * blockDim.x + threadIdx.x;   // 0..2559
    float v;
    if (i < NF) v = gx[(size_t)g * NF + i];
    else        v = pooled[(size_t)g * NH + (i - NF)] / fmaxf(cnt[g], 1.0f);
    comb[(size_t)g * NCOMB + i] = v;
}

__global__ __launch_bounds__(256)
void k_mlp1(const float* __restrict__ comb, const float* __restrict__ fw1,
            const float* __restrict__ fb1, float* __restrict__ hid) {
    __shared__ float sc[NCOMB];
    int g = blockIdx.y;
    for (int i = threadIdx.x; i < NCOMB; i += blockDim.x)
        sc[i] = comb[(size_t)g * NCOMB + i];
    __syncthreads();
    int j = blockIdx.x * blockDim.x + threadIdx.x;   // 0..1023
    float acc = 0.f;
#pragma unroll 4
    for (int k = 0; k < NCOMB; k++) acc += sc[k] * fw1[(size_t)k * NFUSE + j];
    hid[(size_t)g * NFUSE + j] = fmaxf(acc + fb1[j], 0.f);
}

__global__ __launch_bounds__(128)
void k_mlp2(const float* __restrict__ hid, const float* __restrict__ fw2,
            const float* __restrict__ fb2, float* __restrict__ out) {
    __shared__ float sh[NFUSE];
    int g = blockIdx.x;
    for (int i = threadIdx.x; i < NFUSE; i += blockDim.x)
        sh[i] = hid[(size_t)g * NFUSE + i];
    __syncthreads();
    int c = threadIdx.x;
    if (c < NC) {
        float acc = 0.f;
#pragma unroll 4
        for (int k = 0; k < NFUSE; k++) acc += sh[k] * fw2[(size_t)k * NC + c];
        out[(size_t)g * NC + c] = acc + fb2[c];
    }
}

// ---------------- launch ----------------------------------------------------
extern "C" void kernel_launch(void* const* d_in, const int* in_sizes, int n_in,
                              void* d_out, int out_size) {
    const float* gx   = (const float*)d_in[0];   // [64,1536]
    const float* x    = (const float*)d_in[1];   // [50000,1536]
    const int*   eidx = (const int*)  d_in[2];   // [2,200000]
    const int*   batch= (const int*)  d_in[3];   // [50000]
    const float* W1   = (const float*)d_in[4];
    const float* b1   = (const float*)d_in[5];
    const float* W2   = (const float*)d_in[6];
    const float* b2   = (const float*)d_in[7];
    const float* fw1  = (const float*)d_in[8];
    const float* fb1  = (const float*)d_in[9];
    const float* fw2  = (const float*)d_in[10];
    const float* fb2  = (const float*)d_in[11];
    float* out = (float*)d_out;

    const int* src = eidx;
    const int* dst = eidx + NEDGE;

    float *buf1, *buf2, *deg, *dis, *norm, *pooled, *cnt, *comb, *hid;
    cudaGetSymbolAddress((void**)&buf1,   g_buf1);
    cudaGetSymbolAddress((void**)&buf2,   g_buf2);
    cudaGetSymbolAddress((void**)&deg,    g_deg);
    cudaGetSymbolAddress((void**)&dis,    g_dis);
    cudaGetSymbolAddress((void**)&norm,   g_norm);
    cudaGetSymbolAddress((void**)&pooled, g_pooled);
    cudaGetSymbolAddress((void**)&cnt,    g_cnt);
    cudaGetSymbolAddress((void**)&comb,   g_comb);
    cudaGetSymbolAddress((void**)&hid,    g_hid);

    const int TPB = 256;
    const int nodeBlocks = (NNODE + TPB - 1) / TPB;
    const int edgeBlocks = (NEDGE + TPB - 1) / TPB;
    const size_t vec4 = (size_t)NNODE * (NH / 4);          // 12.8M
    const int vecBlocks = (int)((vec4 + TPB - 1) / TPB);   // 50000

    // normalization coefficients
    k_deg_init <<<nodeBlocks, TPB>>>(deg);
    k_deg_count<<<edgeBlocks, TPB>>>(dst, deg);
    k_dis      <<<nodeBlocks, TPB>>>(deg, dis);
    k_norm     <<<edgeBlocks, TPB>>>(src, dst, dis, norm);

    dim3 g1(NH / 128, (NNODE + 127) / 128);

    // conv1: buf1 = x @ W1 ; buf2 = A_hat buf1 ; relu(+b1)
    sgemm128  <<<g1, 256>>>(x, W1, buf1, NNODE, NH, NF);
    k_selfloop<<<vecBlocks, TPB>>>(buf1, dis, buf2);
    k_scatter <<<NEDGE, 256>>>(buf1, buf2, src, dst, norm);
    k_bias_relu<<<vecBlocks, TPB>>>(buf2, b1);

    // conv2: buf1 = buf2 @ W2 ; buf2 = A_hat buf1 ; relu(+b2)
    sgemm128  <<<g1, 256>>>(buf2, W2, buf1, NNODE, NH, NH);
    k_selfloop<<<vecBlocks, TPB>>>(buf1, dis, buf2);
    k_scatter <<<NEDGE, 256>>>(buf1, buf2, src, dst, norm);
    k_bias_relu<<<vecBlocks, TPB>>>(buf2, b2);

    // mean pool per graph
    k_zero_pool<<<(NG * NH + TPB - 1) / TPB, TPB>>>(pooled, cnt);
    k_count    <<<nodeBlocks, TPB>>>(batch, cnt);
    k_pool     <<<NNODE, 256>>>(buf2, batch, pooled);

    // head
    dim3 gc(NCOMB / TPB, NG);
    k_comb<<<gc, TPB>>>(gx, pooled, cnt, comb);
    dim3 gm(NFUSE / TPB, NG);
    k_mlp1<<<gm, TPB>>>(comb, fw1, fb1, hid);
    k_mlp2<<<NG, 128>>>(hid, fw2, fb2, out);
}

// round 2
// speedup vs baseline: 1.6574x; 1.6574x over previous
#include <cuda_runtime.h>
#include <cstdint>

#define NNODE 50000
#define NEDGE 200000
#define NG    64
#define NF    1536
#define NH    1024
#define NC    80
#define NFUSE 1024
#define NCOMB (NF + NH)   // 2560

// ---------------- scratch (device globals; no allocation allowed) ----------
__device__ float g_buf1[(size_t)NNODE * NH];   // 204.8 MB
__device__ float g_buf2[(size_t)NNODE * NH];   // 204.8 MB
__device__ float g_deg [NNODE];
__device__ float g_dis [NNODE];
__device__ float g_norm[NEDGE];
__device__ float g_pooled[NG * NH];
__device__ float g_cnt [NG];
__device__ float g_comb[NG * NCOMB];
__device__ float g_hid [NG * NFUSE];

// ---------------- degree / normalization ----------------------------------
__global__ void k_deg_init(float* deg) {
    int n = blockIdx.x * blockDim.x + threadIdx.x;
    if (n < NNODE) deg[n] = 1.0f;                 // self-loop
}

__global__ void k_deg_count(const int* __restrict__ dst, float* deg) {
    int e = blockIdx.x * blockDim.x + threadIdx.x;
    if (e < NEDGE) atomicAdd(&deg[dst[e]], 1.0f);
}

__global__ void k_dis(const float* __restrict__ deg, float* dis) {
    int n = blockIdx.x * blockDim.x + threadIdx.x;
    if (n < NNODE) dis[n] = rsqrtf(deg[n]);
}

__global__ void k_norm(const int* __restrict__ src, const int* __restrict__ dst,
                       const float* __restrict__ dis, float* norm) {
    int e = blockIdx.x * blockDim.x + threadIdx.x;
    if (e < NEDGE) norm[e] = dis[src[e]] * dis[dst[e]];
}

// ---------------- TF32 tensor-core GEMM ------------------------------------
// C[M,N] = A[M,K] @ B[K,N], row-major. BM=128, BN=128, BK=16, 256 threads,
// 8 warps in 2(m) x 4(n), warp tile 64x32 = 4x4 m16n8k8 fragments.

__device__ __forceinline__ float to_tf32(float x) {
    uint32_t u;
    asm("cvt.rna.tf32.f32 %0, %1;" : "=r"(u) : "f"(x));
    return __uint_as_float(u);
}

__device__ __forceinline__ void mma_tf32(float c[4], const uint32_t a[4],
                                         const uint32_t b[2]) {
    asm volatile(
        "mma.sync.aligned.m16n8k8.row.col.f32.tf32.tf32.f32 "
        "{%0,%1,%2,%3}, {%4,%5,%6,%7}, {%8,%9}, {%0,%1,%2,%3};"
        : "+f"(c[0]), "+f"(c[1]), "+f"(c[2]), "+f"(c[3])
        : "r"(a[0]), "r"(a[1]), "r"(a[2]), "r"(a[3]), "r"(b[0]), "r"(b[1]));
}

__global__ __launch_bounds__(256)
void gemm_tf32(const float* __restrict__ A, const float* __restrict__ B,
               float* __restrict__ C, int M, int N, int K) {
    __shared__ float As[128][20];   // [m][k], stride 20 -> conflict-free frags
    __shared__ float Bs[16][136];   // [k][n], stride 136 -> conflict-free frags

    const int tid  = threadIdx.x;
    const int lane = tid & 31;
    const int warp = tid >> 5;
    const int wm   = (warp & 1) * 64;
    const int wn   = (warp >> 1) * 32;
    const int grp  = lane >> 2;     // 0..7
    const int thr  = lane & 3;      // 0..3

    const int rowBase = blockIdx.y * 128;
    const int colBase = blockIdx.x * 128;

    // A tile: 128 rows x 16 k; 2 threads/row, 8 consecutive k each
    const int arow = tid >> 1;
    const int acol = (tid & 1) * 8;
    const bool aValid = (rowBase + arow) < M;
    const float* Ap = A + (size_t)(rowBase + arow) * K + acol;

    // B tile: 16 k-rows x 128 cols; 16 threads/row, 8 consecutive n each
    const int brow = tid >> 4;
    const int bcol = (tid & 15) * 8;
    const float* Bp = B + (size_t)brow * N + colBase + bcol;

    const float4 z4 = make_float4(0.f, 0.f, 0.f, 0.f);
    float4 ra0 = aValid ? *(const float4*)(Ap)     : z4;
    float4 ra1 = aValid ? *(const float4*)(Ap + 4) : z4;
    float4 rb0 = *(const float4*)(Bp);
    float4 rb1 = *(const float4*)(Bp + 4);

    float acc[4][4][4];
#pragma unroll
    for (int i = 0; i < 4; i++)
#pragma unroll
        for (int j = 0; j < 4; j++)
#pragma unroll
            for (int r = 0; r < 4; r++) acc[i][j][r] = 0.f;

    for (int k0 = 0; k0 < K; k0 += 16) {
        __syncthreads();   // previous iter's smem reads complete
        // store (with tf32 rounding)
        As[arow][acol + 0] = to_tf32(ra0.x);
        As[arow][acol + 1] = to_tf32(ra0.y);
        As[arow][acol + 2] = to_tf32(ra0.z);
        As[arow][acol + 3] = to_tf32(ra0.w);
        As[arow][acol + 4] = to_tf32(ra1.x);
        As[arow][acol + 5] = to_tf32(ra1.y);
        As[arow][acol + 6] = to_tf32(ra1.z);
        As[arow][acol + 7] = to_tf32(ra1.w);
        *(float4*)&Bs[brow][bcol]     = make_float4(to_tf32(rb0.x), to_tf32(rb0.y),
                                                    to_tf32(rb0.z), to_tf32(rb0.w));
        *(float4*)&Bs[brow][bcol + 4] = make_float4(to_tf32(rb1.x), to_tf32(rb1.y),
                                                    to_tf32(rb1.z), to_tf32(rb1.w));
        __syncthreads();

        // prefetch next tile while computing
        if (k0 + 16 < K) {
            ra0 = aValid ? *(const float4*)(Ap + k0 + 16)     : z4;
            ra1 = aValid ? *(const float4*)(Ap + k0 + 16 + 4) : z4;
            rb0 = *(const float4*)(Bp + (size_t)(k0 + 16) * N);
            rb1 = *(const float4*)(Bp + (size_t)(k0 + 16) * N + 4);
        }

#pragma unroll
        for (int kk = 0; kk < 2; kk++) {
            const int kb = kk * 8;
            uint32_t af[4][4], bf[4][2];
#pragma unroll
            for (int mi = 0; mi < 4; mi++) {
                int m = wm + mi * 16 + grp;
                af[mi][0] = __float_as_uint(As[m][kb + thr]);
                af[mi][1] = __float_as_uint(As[m + 8][kb + thr]);
                af[mi][2] = __float_as_uint(As[m][kb + 4 + thr]);
                af[mi][3] = __float_as_uint(As[m + 8][kb + 4 + thr]);
            }
#pragma unroll
            for (int ni = 0; ni < 4; ni++) {
                int n = wn + ni * 8 + grp;
                bf[ni][0] = __float_as_uint(Bs[kb + thr][n]);
                bf[ni][1] = __float_as_uint(Bs[kb + 4 + thr][n]);
            }
#pragma unroll
            for (int mi = 0; mi < 4; mi++)
#pragma unroll
                for (int ni = 0; ni < 4; ni++)
                    mma_tf32(acc[mi][ni], af[mi], bf[ni]);
        }
    }

    // epilogue: c0,c1 at (grp, 2*thr), c2,c3 at (grp+8, 2*thr)
#pragma unroll
    for (int mi = 0; mi < 4; mi++) {
#pragma unroll
        for (int ni = 0; ni < 4; ni++) {
            int m0 = rowBase + wm + mi * 16 + grp;
            int n0 = colBase + wn + ni * 8 + thr * 2;
            if (m0 < M)
                *(float2*)&C[(size_t)m0 * N + n0] =
                    make_float2(acc[mi][ni][0], acc[mi][ni][1]);
            if (m0 + 8 < M)
                *(float2*)&C[(size_t)(m0 + 8) * N + n0] =
                    make_float2(acc[mi][ni][2], acc[mi][ni][3]);
        }
    }
}

// ---------------- message passing ------------------------------------------
__global__ void k_selfloop(const float* __restrict__ in, const float* __restrict__ dis,
                           float* __restrict__ out) {
    size_t idx = (size_t)blockIdx.x * blockDim.x + threadIdx.x;   // over N*NH/4
    if (idx >= (size_t)NNODE * (NH / 4)) return;
    int n = (int)(idx >> 8);                  // NH/4 == 256
    float s = dis[n] * dis[n];
    float4 v = ((const float4*)in)[idx];
    v.x *= s; v.y *= s; v.z *= s; v.w *= s;
    ((float4*)out)[idx] = v;
}

__global__ __launch_bounds__(256)
void k_scatter(const float* __restrict__ in, float* __restrict__ out,
               const int* __restrict__ src, const int* __restrict__ dst,
               const float* __restrict__ norm) {
    int e = blockIdx.x;
    float w = norm[e];
    const float4* ip = (const float4*)(in + (size_t)src[e] * NH);
    float* op = out + (size_t)dst[e] * NH + threadIdx.x * 4;
    float4 v = ip[threadIdx.x];
    atomicAdd(op + 0, v.x * w);
    atomicAdd(op + 1, v.y * w);
    atomicAdd(op + 2, v.z * w);
    atomicAdd(op + 3, v.w * w);
}

__global__ void k_bias_relu(float* __restrict__ x, const float* __restrict__ b) {
    size_t idx = (size_t)blockIdx.x * blockDim.x + threadIdx.x;   // over N*NH/4
    if (idx >= (size_t)NNODE * (NH / 4)) return;
    int h = ((int)idx & (NH / 4 - 1)) * 4;
    float4 v = ((float4*)x)[idx];
    v.x = fmaxf(v.x + b[h + 0], 0.f);
    v.y = fmaxf(v.y + b[h + 1], 0.f);
    v.z = fmaxf(v.z + b[h + 2], 0.f);
    v.w = fmaxf(v.w + b[h + 3], 0.f);
    ((float4*)x)[idx] = v;
}

// ---------------- pooling + head -------------------------------------------
__global__ void k_zero_pool(float* pooled, float* cnt) {
    int i = blockIdx.x * blockDim.x + threadIdx.x;
    if (i < NG * NH) pooled[i] = 0.f;
    if (i < NG) cnt[i] = 0.f;
}

__global__ void k_count(const int* __restrict__ batch, float* cnt) {
    int n = blockIdx.x * blockDim.x + threadIdx.x;
    if (n < NNODE) atomicAdd(&cnt[batch[n]], 1.0f);
}

__global__ __launch_bounds__(256)
void k_pool(const float* __restrict__ a, const int* __restrict__ batch,
            float* __restrict__ pooled) {
    int n = blockIdx.x;
    int g = batch[n];
    float4 v = ((const float4*)(a + (size_t)n * NH))[threadIdx.x];
    float* op = pooled + (size_t)g * NH + threadIdx.x * 4;
    atomicAdd(op + 0, v.x);
    atomicAdd(op + 1, v.y);
    atomicAdd(op + 2, v.z);
    atomicAdd(op + 3, v.w);
}

__global__ void k_comb(const float* __restrict__ gx, const float* __restrict__ pooled,
                       const float* __restrict__ cnt, float* __restrict__ comb) {
    int g = blockIdx.y;
    int i = blockIdx.x * blockDim.x + threadIdx.x;   // 0..2559
    float v;
    if (i < NF) v = gx[(size_t)g * NF + i];
    else        v = pooled[(size_t)g * NH + (i - NF)] / fmaxf(cnt[g], 1.0f);
    comb[(size_t)g * NCOMB + i] = v;
}

__global__ __launch_bounds__(256)
void k_mlp1(const float* __restrict__ comb, const float* __restrict__ fw1,
            const float* __restrict__ fb1, float* __restrict__ hid) {
    __shared__ float sc[NCOMB];
    int g = blockIdx.y;
    for (int i = threadIdx.x; i < NCOMB; i += blockDim.x)
        sc[i] = comb[(size_t)g * NCOMB + i];
    __syncthreads();
    int j = blockIdx.x * blockDim.x + threadIdx.x;   // 0..1023
    float acc = 0.f;
#pragma unroll 4
    for (int k = 0; k < NCOMB; k++) acc += sc[k] * fw1[(size_t)k * NFUSE + j];
    hid[(size_t)g * NFUSE + j] = fmaxf(acc + fb1[j], 0.f);
}

__global__ __launch_bounds__(128)
void k_mlp2(const float* __restrict__ hid, const float* __restrict__ fw2,
            const float* __restrict__ fb2, float* __restrict__ out) {
    __shared__ float sh[NFUSE];
    int g = blockIdx.x;
    for (int i = threadIdx.x; i < NFUSE; i += blockDim.x)
        sh[i] = hid[(size_t)g * NFUSE + i];
    __syncthreads();
    int c = threadIdx.x;
    if (c < NC) {
        float acc = 0.f;
#pragma unroll 4
        for (int k = 0; k < NFUSE; k++) acc += sh[k] * fw2[(size_t)k * NC + c];
        out[(size_t)g * NC + c] = acc + fb2[c];
    }
}

// ---------------- launch ----------------------------------------------------
extern "C" void kernel_launch(void* const* d_in, const int* in_sizes, int n_in,
                              void* d_out, int out_size) {
    const float* gx   = (const float*)d_in[0];   // [64,1536]
    const float* x    = (const float*)d_in[1];   // [50000,1536]
    const int*   eidx = (const int*)  d_in[2];   // [2,200000]
    const int*   batch= (const int*)  d_in[3];   // [50000]
    const float* W1   = (const float*)d_in[4];
    const float* b1   = (const float*)d_in[5];
    const float* W2   = (const float*)d_in[6];
    const float* b2   = (const float*)d_in[7];
    const float* fw1  = (const float*)d_in[8];
    const float* fb1  = (const float*)d_in[9];
    const float* fw2  = (const float*)d_in[10];
    const float* fb2  = (const float*)d_in[11];
    float* out = (float*)d_out;

    const int* src = eidx;
    const int* dst = eidx + NEDGE;

    float *buf1, *buf2, *deg, *dis, *norm, *pooled, *cnt, *comb, *hid;
    cudaGetSymbolAddress((void**)&buf1,   g_buf1);
    cudaGetSymbolAddress((void**)&buf2,   g_buf2);
    cudaGetSymbolAddress((void**)&deg,    g_deg);
    cudaGetSymbolAddress((void**)&dis,    g_dis);
    cudaGetSymbolAddress((void**)&norm,   g_norm);
    cudaGetSymbolAddress((void**)&pooled, g_pooled);
    cudaGetSymbolAddress((void**)&cnt,    g_cnt);
    cudaGetSymbolAddress((void**)&comb,   g_comb);
    cudaGetSymbolAddress((void**)&hid,    g_hid);

    const int TPB = 256;
    const int nodeBlocks = (NNODE + TPB - 1) / TPB;
    const int edgeBlocks = (NEDGE + TPB - 1) / TPB;
    const size_t vec4 = (size_t)NNODE * (NH / 4);          // 12.8M
    const int vecBlocks = (int)((vec4 + TPB - 1) / TPB);   // 50000

    // normalization coefficients
    k_deg_init <<<nodeBlocks, TPB>>>(deg);
    k_deg_count<<<edgeBlocks, TPB>>>(dst, deg);
    k_dis      <<<nodeBlocks, TPB>>>(deg, dis);
    k_norm     <<<edgeBlocks, TPB>>>(src, dst, dis, norm);

    dim3 g1(NH / 128, (NNODE + 127) / 128);   // (8, 391)

    // conv1: buf1 = x @ W1 ; buf2 = A_hat buf1 ; relu(+b1)
    gemm_tf32 <<<g1, 256>>>(x, W1, buf1, NNODE, NH, NF);
    k_selfloop<<<vecBlocks, TPB>>>(buf1, dis, buf2);
    k_scatter <<<NEDGE, 256>>>(buf1, buf2, src, dst, norm);
    k_bias_relu<<<vecBlocks, TPB>>>(buf2, b1);

    // conv2: buf1 = buf2 @ W2 ; buf2 = A_hat buf1 ; relu(+b2)
    gemm_tf32 <<<g1, 256>>>(buf2, W2, buf1, NNODE, NH, NH);
    k_selfloop<<<vecBlocks, TPB>>>(buf1, dis, buf2);
    k_scatter <<<NEDGE, 256>>>(buf1, buf2, src, dst, norm);
    k_bias_relu<<<vecBlocks, TPB>>>(buf2, b2);

    // mean pool per graph
    k_zero_pool<<<(NG * NH + TPB - 1) / TPB, TPB>>>(pooled, cnt);
    k_count    <<<nodeBlocks, TPB>>>(batch, cnt);
    k_pool     <<<NNODE, 256>>>(buf2, batch, pooled);

    // head
    dim3 gc(NCOMB / TPB, NG);
    k_comb<<<gc, TPB>>>(gx, pooled, cnt, comb);
    dim3 gm(NFUSE / TPB, NG);
    k_mlp1<<<gm, TPB>>>(comb, fw1, fb1, hid);
    k_mlp2<<<NG, 128>>>(hid, fw2, fb2, out);
}

// round 4
// speedup vs baseline: 1.8952x; 1.1435x over previous
#include <cuda_runtime.h>
#include <cstdint>

#define NNODE 50000
#define NEDGE 200000
#define NG    64
#define NF    1536
#define NH    1024
#define NC    80
#define NFUSE 1024
#define NCOMB (NF + NH)   // 2560

// ---------------- scratch (device globals) ----------------------------------
__device__ float g_buf1[(size_t)NNODE * NH];
__device__ float g_buf2[(size_t)NNODE * NH];
__device__ float g_buf3[(size_t)NNODE * NH];
__device__ float g_wt1 [(size_t)NH * NF];      // W1^T [N=1024, K=1536], tf32-rounded
__device__ float g_wt2 [(size_t)NH * NH];      // W2^T [1024, 1024], tf32-rounded
__device__ float g_deg [NNODE];
__device__ float g_dis [NNODE];
__device__ float g_norm[NEDGE];
__device__ float g_pooled[NG * NH];
__device__ float g_cnt [NG];
__device__ float g_comb[NG * NCOMB];
__device__ float g_hid [NG * NFUSE];

// ---------------- helpers ----------------------------------------------------
__device__ __forceinline__ uint32_t smem_u32(const void* p) {
    uint32_t a;
    asm("{ .reg .u64 t; cvta.to.shared.u64 t, %1; cvt.u32.u64 %0, t; }"
        : "=r"(a) : "l"(p));
    return a;
}

__device__ __forceinline__ float to_tf32(float x) {
    uint32_t u;
    asm("cvt.rna.tf32.f32 %0, %1;" : "=r"(u) : "f"(x));
    return __uint_as_float(u);
}

__device__ __forceinline__ void mma_tf32(float c[4], const uint32_t a[4],
                                         const uint32_t b[2]) {
    asm volatile(
        "mma.sync.aligned.m16n8k8.row.col.f32.tf32.tf32.f32 "
        "{%0,%1,%2,%3}, {%4,%5,%6,%7}, {%8,%9}, {%0,%1,%2,%3};"
        : "+f"(c[0]), "+f"(c[1]), "+f"(c[2]), "+f"(c[3])
        : "r"(a[0]), "r"(a[1]), "r"(a[2]), "r"(a[3]), "r"(b[0]), "r"(b[1]));
}

#define CP_ASYNC16(dst, src, sz) \
    asm volatile("cp.async.cg.shared.global [%0], [%1], 16, %2;" \
                 :: "r"(dst), "l"(src), "r"(sz) : "memory")
#define CP_COMMIT()  asm volatile("cp.async.commit_group;" ::: "memory")
#define CP_WAIT(n)   asm volatile("cp.async.wait_group %0;" :: "n"(n) : "memory")

// ---------------- tf32 mma.sync GEMM -----------------------------------------
// C[M,1024] = A[M,K] @ Bt[1024,K]^T.  CTA tile 128x256, BK=32, 512 threads
// (16 warps: 2m x 8n, warp tile 64x32, 4x4 m16n8k8 frags), 2-stage cp.async.
// Fused epilogue: C = result, C2 = result * dis[m]^2 (GCN self-loop init).
#define AS_STRIDE 36
#define BS_STRIDE 264
#define AS_FLOATS (128 * AS_STRIDE)          // 4608
#define BS_FLOATS (32 * BS_STRIDE)           // 8448
#define STAGE_FLOATS (AS_FLOATS + BS_FLOATS) // 13056
#define GEMM_SMEM (2 * STAGE_FLOATS * 4)     // 104448 B

__global__ __launch_bounds__(512, 1)
void gemm_mma(const float* __restrict__ A, const float* __restrict__ Bt,
              float* __restrict__ C, float* __restrict__ C2,
              const float* __restrict__ dis, int M, int K, int nChunk) {
    extern __shared__ float sm[];
    const uint32_t smb = smem_u32(sm);

    const int tid  = threadIdx.x;
    const int lane = tid & 31;
    const int warp = tid >> 5;            // 0..15
    const int wm   = (warp & 1) * 64;
    const int wn   = (warp >> 1) * 32;    // 0..224
    const int grp  = lane >> 2;           // 0..7
    const int thr  = lane & 3;            // 0..3

    const int rowBase = blockIdx.y * 128;
    const int colBase = blockIdx.x * 256;

    // issue cp.async loads of chunk -> stage st (0/1)
    auto issue = [&](int chunk, int st) {
        const uint32_t base = smb + (uint32_t)st * (STAGE_FLOATS * 4);
        const int k0 = chunk * 32;
#pragma unroll
        for (int t = tid; t < 3072; t += 512) {
            if (t < 1024) {                       // A: 128 rows x 8 16B chunks
                int r = t >> 3, c = t & 7;
                uint32_t dst = base + (uint32_t)(r * AS_STRIDE + c * 4) * 4u;
                int row = rowBase + r;
                int ok  = row < M;
                const float* src = A + (size_t)(ok ? row : 0) * K + k0 + c * 4;
                CP_ASYNC16(dst, src, ok ? 16 : 0);
            } else {                              // B: 32 k-rows x 64 16B chunks
                int t2 = t - 1024;
                int kk = t2 >> 6, c = t2 & 63;
                uint32_t dst = base + (uint32_t)(AS_FLOATS + kk * BS_STRIDE + c * 4) * 4u;
                const float* src = Bt + (size_t)(colBase + c * 4) * K;  // placeholder
                // B stored [k][n] in smem, gathered from Bt[n][k]: need 4 rows of Bt.
                // Instead: transpose-free gather is 4 separate loads; use scalar path:
                (void)src;
                // handled below
                // (unreachable marker)
                CP_ASYNC16(dst, Bt, 0);
            }
        }
    };
    (void)issue;

    // NOTE: B needs [k][n] layout in smem but Bt is [n][k] in gmem; a 16B
    // cp.async along n would need Bt in [k][n]. So we keep B smem as [k][n]
    // but load from the ORIGINAL row-major W via the second operand below.
    // To keep it simple and fast, Bt here is actually passed as W in [K,N]
    // row-major (k-major rows), so 16B chunks along n are contiguous.

    auto issue2 = [&](int chunk, int st) {
        const uint32_t base = smb + (uint32_t)st * (STAGE_FLOATS * 4);
        const int k0 = chunk * 32;
#pragma unroll
        for (int t = tid; t < 3072; t += 512) {
            if (t < 1024) {                       // A: 128 rows x 8 16B chunks
                int r = t >> 3, c = t & 7;
                uint32_t dst = base + (uint32_t)(r * AS_STRIDE + c * 4) * 4u;
                int row = rowBase + r;
                int ok  = row < M;
                const float* src = A + (size_t)(ok ? row : 0) * K + k0 + c * 4;
                CP_ASYNC16(dst, src, ok ? 16 : 0);
            } else {                              // B[k][n]: from W[K,N] rows
                int t2 = t - 1024;
                int kk = t2 >> 6, c = t2 & 63;    // kk 0..31, c*4 = n offset
                uint32_t dst = base + (uint32_t)(AS_FLOATS + kk * BS_STRIDE + c * 4) * 4u;
                const float* src = Bt + (size_t)(k0 + kk) * NH + colBase + c * 4;
                CP_ASYNC16(dst, src, 16);
            }
        }
    };

    float acc[4][4][4];
#pragma unroll
    for (int i = 0; i < 4; i++)
#pragma unroll
        for (int j = 0; j < 4; j++)
#pragma unroll
            for (int r = 0; r < 4; r++) acc[i][j][r] = 0.f;

    issue2(0, 0);
    CP_COMMIT();

    for (int i = 0; i < nChunk; i++) {
        const int si = i & 1;
        if (i + 1 < nChunk) {
            issue2(i + 1, si ^ 1);
            CP_COMMIT();
            CP_WAIT(1);
        } else {
            CP_WAIT(0);
        }
        __syncthreads();

        const float* As = sm + si * STAGE_FLOATS;            // [128][36]
        const float* Bs = sm + si * STAGE_FLOATS + AS_FLOATS; // [32][264]

#pragma unroll
        for (int kk = 0; kk < 4; kk++) {
            const int kb = kk * 8;
            uint32_t af[4][4], bf[4][2];
#pragma unroll
            for (int mi = 0; mi < 4; mi++) {
                int m = wm + mi * 16 + grp;
                af[mi][0] = __float_as_uint(As[m * AS_STRIDE + kb + thr]);
                af[mi][1] = __float_as_uint(As[(m + 8) * AS_STRIDE + kb + thr]);
                af[mi][2] = __float_as_uint(As[m * AS_STRIDE + kb + 4 + thr]);
                af[mi][3] = __float_as_uint(As[(m + 8) * AS_STRIDE + kb + 4 + thr]);
            }
#pragma unroll
            for (int ni = 0; ni < 4; ni++) {
                int n = wn + ni * 8 + grp;
                bf[ni][0] = __float_as_uint(Bs[(kb + thr) * BS_STRIDE + n]);
                bf[ni][1] = __float_as_uint(Bs[(kb + 4 + thr) * BS_STRIDE + n]);
            }
#pragma unroll
            for (int mi = 0; mi < 4; mi++)
#pragma unroll
                for (int ni = 0; ni < 4; ni++)
                    mma_tf32(acc[mi][ni], af[mi], bf[ni]);
        }
        __syncthreads();
    }

    // epilogue: dual store (raw C, and C2 = C * dis^2)
#pragma unroll
    for (int mi = 0; mi < 4; mi++) {
        int m0 = rowBase + wm + mi * 16 + grp;
        int m1 = m0 + 8;
        float s0 = (m0 < M) ? dis[m0] * dis[m0] : 0.f;
        float s1 = (m1 < M) ? dis[m1] * dis[m1] : 0.f;
#pragma unroll
        for (int ni = 0; ni < 4; ni++) {
            int n0 = colBase + wn + ni * 8 + thr * 2;
            if (m0 < M) {
                *(float2*)&C [(size_t)m0 * NH + n0] = make_float2(acc[mi][ni][0], acc[mi][ni][1]);
                *(float2*)&C2[(size_t)m0 * NH + n0] = make_float2(acc[mi][ni][0] * s0, acc[mi][ni][1] * s0);
            }
            if (m1 < M) {
                *(float2*)&C [(size_t)m1 * NH + n0] = make_float2(acc[mi][ni][2], acc[mi][ni][3]);
                *(float2*)&C2[(size_t)m1 * NH + n0] = make_float2(acc[mi][ni][2] * s1, acc[mi][ni][3] * s1);
            }
        }
    }
}

// ---------------- weight prep: tf32-round in place layout [K,N] --------------
__global__ void k_round_tf32(const float* __restrict__ W, float* __restrict__ Wr,
                             int total) {
    int i = blockIdx.x * blockDim.x + threadIdx.x;
    if (i < total) Wr[i] = to_tf32(W[i]);
}

// ---------------- degree / normalization ------------------------------------
__global__ void k_deg_init(float* deg) {
    int n = blockIdx.x * blockDim.x + threadIdx.x;
    if (n < NNODE) deg[n] = 1.0f;
}

__global__ void k_deg_count(const int* __restrict__ dst, float* deg) {
    int e = blockIdx.x * blockDim.x + threadIdx.x;
    if (e < NEDGE) atomicAdd(&deg[dst[e]], 1.0f);
}

__global__ void k_dis(const float* __restrict__ deg, float* dis) {
    int n = blockIdx.x * blockDim.x + threadIdx.x;
    if (n < NNODE) dis[n] = rsqrtf(deg[n]);
}

__global__ void k_norm(const int* __restrict__ src, const int* __restrict__ dst,
                       const float* __restrict__ dis, float* norm) {
    int e = blockIdx.x * blockDim.x + threadIdx.x;
    if (e < NEDGE) norm[e] = dis[src[e]] * dis[dst[e]];
}

// ---------------- message passing --------------------------------------------
__global__ __launch_bounds__(256)
void k_scatter(const float* __restrict__ in, float* __restrict__ out,
               const int* __restrict__ src, const int* __restrict__ dst,
               const float* __restrict__ norm) {
    int e = blockIdx.x;
    float w = norm[e];
    const float4* ip = (const float4*)(in + (size_t)src[e] * NH);
    float* op = out + (size_t)dst[e] * NH + threadIdx.x * 4;
    float4 v = ip[threadIdx.x];
    atomicAdd(op + 0, v.x * w);
    atomicAdd(op + 1, v.y * w);
    atomicAdd(op + 2, v.z * w);
    atomicAdd(op + 3, v.w * w);
}

__global__ void k_bias_relu(float* __restrict__ x, const float* __restrict__ b) {
    size_t idx = (size_t)blockIdx.x * blockDim.x + threadIdx.x;
    if (idx >= (size_t)NNODE * (NH / 4)) return;
    int h = ((int)idx & (NH / 4 - 1)) * 4;
    float4 v = ((float4*)x)[idx];
    v.x = fmaxf(v.x + b[h + 0], 0.f);
    v.y = fmaxf(v.y + b[h + 1], 0.f);
    v.z = fmaxf(v.z + b[h + 2], 0.f);
    v.w = fmaxf(v.w + b[h + 3], 0.f);
    ((float4*)x)[idx] = v;
}

// ---------------- pooling (fused bias2 + relu) + head ------------------------
__global__ void k_zero_pool(float* pooled, float* cnt) {
    int i = blockIdx.x * blockDim.x + threadIdx.x;
    if (i < NG * NH) pooled[i] = 0.f;
    if (i < NG) cnt[i] = 0.f;
}

__global__ void k_count(const int* __restrict__ batch, float* cnt) {
    int n = blockIdx.x * blockDim.x + threadIdx.x;
    if (n < NNODE) atomicAdd(&cnt[batch[n]], 1.0f);
}

__global__ __launch_bounds__(256)
void k_pool(const float* __restrict__ a, const int* __restrict__ batch,
            const float* __restrict__ b, float* __restrict__ pooled) {
    int n = blockIdx.x;
    int g = batch[n];
    int h = threadIdx.x * 4;
    float4 v = ((const float4*)(a + (size_t)n * NH))[threadIdx.x];
    v.x = fmaxf(v.x + b[h + 0], 0.f);
    v.y = fmaxf(v.y + b[h + 1], 0.f);
    v.z = fmaxf(v.z + b[h + 2], 0.f);
    v.w = fmaxf(v.w + b[h + 3], 0.f);
    float* op = pooled + (size_t)g * NH + h;
    atomicAdd(op + 0, v.x);
    atomicAdd(op + 1, v.y);
    atomicAdd(op + 2, v.z);
    atomicAdd(op + 3, v.w);
}

__global__ void k_comb(const float* __restrict__ gx, const float* __restrict__ pooled,
                       const float* __restrict__ cnt, float* __restrict__ comb) {
    int g = blockIdx.y;
    int i = blockIdx.x * blockDim.x + threadIdx.x;
    float v;
    if (i < NF) v = gx[(size_t)g * NF + i];
    else        v = pooled[(size_t)g * NH + (i - NF)] / fmaxf(cnt[g], 1.0f);
    comb[(size_t)g * NCOMB + i] = v;
}

// hid[g][j] = relu(comb[g,:] @ fw1[:,j] + fb1[j]); fw1 read once total.
__global__ __launch_bounds__(256)
void k_mlp1(const float* __restrict__ comb, const float* __restrict__ fw1,
            const float* __restrict__ fb1, float* __restrict__ hid) {
    __shared__ float sc[32][65];
    int j  = blockIdx.x * 16 + (threadIdx.x & 15);
    int gq = threadIdx.x >> 4;                 // 0..15, g = gq*4+q
    float acc[4] = {0.f, 0.f, 0.f, 0.f};
    for (int kb = 0; kb < NCOMB; kb += 32) {
#pragma unroll
        for (int u = 0; u < 8; u++) {
            int l = threadIdx.x + 256 * u;
            int g = l >> 5, kk = l & 31;
            sc[kk][g] = comb[(size_t)g * NCOMB + kb + kk];
        }
        __syncthreads();
#pragma unroll 8
        for (int kk = 0; kk < 32; kk++) {
            float w = fw1[(size_t)(kb + kk) * NFUSE + j];
#pragma unroll
            for (int q = 0; q < 4; q++) acc[q] += sc[kk][gq * 4 + q] * w;
        }
        __syncthreads();
    }
#pragma unroll
    for (int q = 0; q < 4; q++) {
        int g = gq * 4 + q;
        hid[(size_t)g * NFUSE + j] = fmaxf(acc[q] + fb1[j], 0.f);
    }
}

__global__ __launch_bounds__(128)
void k_mlp2(const float* __restrict__ hid, const float* __restrict__ fw2,
            const float* __restrict__ fb2, float* __restrict__ out) {
    __shared__ float sh[NFUSE];
    int g = blockIdx.x;
    for (int i = threadIdx.x; i < NFUSE; i += blockDim.x)
        sh[i] = hid[(size_t)g * NFUSE + i];
    __syncthreads();
    int c = threadIdx.x;
    if (c < NC) {
        float acc = 0.f;
#pragma unroll 4
        for (int k = 0; k < NFUSE; k++) acc += sh[k] * fw2[(size_t)k * NC + c];
        out[(size_t)g * NC + c] = acc + fb2[c];
    }
}

// ---------------- launch ------------------------------------------------------
extern "C" void kernel_launch(void* const* d_in, const int* in_sizes, int n_in,
                              void* d_out, int out_size) {
    const float* gx    = (const float*)d_in[0];
    const float* x     = (const float*)d_in[1];
    const int*   eidx  = (const int*)  d_in[2];
    const int*   batch = (const int*)  d_in[3];
    const float* W1    = (const float*)d_in[4];
    const float* b1    = (const float*)d_in[5];
    const float* W2    = (const float*)d_in[6];
    const float* b2    = (const float*)d_in[7];
    const float* fw1   = (const float*)d_in[8];
    const float* fb1   = (const float*)d_in[9];
    const float* fw2   = (const float*)d_in[10];
    const float* fb2   = (const float*)d_in[11];
    float* out = (float*)d_out;

    const int* src = eidx;
    const int* dst = eidx + NEDGE;

    float *buf1, *buf2, *buf3, *wt1, *wt2, *deg, *dis, *norm, *pooled, *cnt, *comb, *hid;
    cudaGetSymbolAddress((void**)&buf1,   g_buf1);
    cudaGetSymbolAddress((void**)&buf2,   g_buf2);
    cudaGetSymbolAddress((void**)&buf3,   g_buf3);
    cudaGetSymbolAddress((void**)&wt1,    g_wt1);
    cudaGetSymbolAddress((void**)&wt2,    g_wt2);
    cudaGetSymbolAddress((void**)&deg,    g_deg);
    cudaGetSymbolAddress((void**)&dis,    g_dis);
    cudaGetSymbolAddress((void**)&norm,   g_norm);
    cudaGetSymbolAddress((void**)&pooled, g_pooled);
    cudaGetSymbolAddress((void**)&cnt,    g_cnt);
    cudaGetSymbolAddress((void**)&comb,   g_comb);
    cudaGetSymbolAddress((void**)&hid,    g_hid);

    cudaFuncSetAttribute(gemm_mma, cudaFuncAttributeMaxDynamicSharedMemorySize,
                         GEMM_SMEM);

    const int TPB = 256;
    const int nodeBlocks = (NNODE + TPB - 1) / TPB;
    const int edgeBlocks = (NEDGE + TPB - 1) / TPB;
    const size_t vec4 = (size_t)NNODE * (NH / 4);
    const int vecBlocks = (int)((vec4 + TPB - 1) / TPB);

    // weights: tf32-round, keep [K,N] row-major (B smem is [k][n])
    k_round_tf32<<<(NF * NH + TPB - 1) / TPB, TPB>>>(W1, wt1, NF * NH);
    k_round_tf32<<<(NH * NH + TPB - 1) / TPB, TPB>>>(W2, wt2, NH * NH);

    // normalization
    k_deg_init <<<nodeBlocks, TPB>>>(deg);
    k_deg_count<<<edgeBlocks, TPB>>>(dst, deg);
    k_dis      <<<nodeBlocks, TPB>>>(deg, dis);
    k_norm     <<<edgeBlocks, TPB>>>(src, dst, dis, norm);

    dim3 gg(NH / 256, (NNODE + 127) / 128);   // (4, 391)

    // conv1: buf1 = x@W1 (raw), buf2 = buf1*dis^2 (fused self-loop init)
    gemm_mma<<<gg, 512, GEMM_SMEM>>>(x, wt1, buf1, buf2, dis, NNODE, NF, NF / 32);
    k_scatter  <<<NEDGE, 256>>>(buf1, buf2, src, dst, norm);
    k_bias_relu<<<vecBlocks, TPB>>>(buf2, b1);

    // conv2: buf1 = buf2@W2 (raw), buf3 = buf1*dis^2
    gemm_mma<<<gg, 512, GEMM_SMEM>>>(buf2, wt2, buf1, buf3, dis, NNODE, NH, NH / 32);
    k_scatter  <<<NEDGE, 256>>>(buf1, buf3, src, dst, norm);

    // mean pool (bias2 + relu fused)
    k_zero_pool<<<(NG * NH + TPB - 1) / TPB, TPB>>>(pooled, cnt);
    k_count    <<<nodeBlocks, TPB>>>(batch, cnt);
    k_pool     <<<NNODE, 256>>>(buf3, batch, b2, pooled);

    // head
    dim3 gc(NCOMB / TPB, NG);
    k_comb<<<gc, TPB>>>(gx, pooled, cnt, comb);
    k_mlp1<<<NFUSE / 16, 256>>>(comb, fw1, fb1, hid);
    k_mlp2<<<NG, 128>>>(hid, fw2, fb2, out);
}

// round 5
// speedup vs baseline: 2.6253x; 1.3852x over previous
#include <cuda_runtime.h>
#include <cstdint>

#define NNODE 50000
#define NEDGE 200000
#define NG    64
#define NF    1536
#define NH    1024
#define NC    80
#define NFUSE 1024
#define NCOMB (NF + NH)   // 2560

// ---------------- scratch (device globals) ----------------------------------
__device__ float g_buf1[(size_t)NNODE * NH];
__device__ float g_buf2[(size_t)NNODE * NH];
__device__ float g_buf3[(size_t)NNODE * NH];
__device__ float g_wt1 [(size_t)NF * NH];      // W1 tf32-rounded [K,N]
__device__ float g_wt2 [(size_t)NH * NH];      // W2 tf32-rounded [K,N]
__device__ float g_deg [NNODE];
__device__ float g_dis [NNODE];
__device__ float g_norm[NEDGE];
__device__ float g_pooled[NG * NH];
__device__ float g_cnt [NG];
__device__ float g_comb[NG * NCOMB];
__device__ float g_hid [NG * NFUSE];

// ---------------- helpers ----------------------------------------------------
__device__ __forceinline__ float to_tf32(float x) {
    uint32_t u;
    asm("cvt.rna.tf32.f32 %0, %1;" : "=r"(u) : "f"(x));
    return __uint_as_float(u);
}

__device__ __forceinline__ void mma_tf32(float c[4], const uint32_t a[4],
                                         const uint32_t b[2]) {
    asm volatile(
        "mma.sync.aligned.m16n8k8.row.col.f32.tf32.tf32.f32 "
        "{%0,%1,%2,%3}, {%4,%5,%6,%7}, {%8,%9}, {%0,%1,%2,%3};"
        : "+f"(c[0]), "+f"(c[1]), "+f"(c[2]), "+f"(c[3])
        : "r"(a[0]), "r"(a[1]), "r"(a[2]), "r"(a[3]), "r"(b[0]), "r"(b[1]));
}

__device__ __forceinline__ void red_add_v4(float* p, float4 v) {
    asm volatile("red.add.v4.f32 [%0], {%1,%2,%3,%4};"
                 :: "l"(p), "f"(v.x), "f"(v.y), "f"(v.z), "f"(v.w) : "memory");
}

#define CP_ASYNC16(dst, src, sz) \
    asm volatile("cp.async.cg.shared.global [%0], [%1], 16, %2;" \
                 :: "r"(dst), "l"(src), "r"(sz) : "memory")
#define CP_COMMIT()  asm volatile("cp.async.commit_group;" ::: "memory")
#define CP_WAIT(n)   asm volatile("cp.async.wait_group %0;" :: "n"(n) : "memory")

// ---------------- tf32 mma.sync GEMM -----------------------------------------
// C[M,1024] = A[M,K] @ W[K,1024].  CTA tile 128x128, BK=32, 128 threads
// (4 warps 2m x 2n, warp tile 64x64 = 4x8 m16n8k8 frags), 2-stage cp.async,
// 2 CTAs/SM. Fused epilogue: C = result, C2 = result * dis[m]^2.
#define AS_STRIDE 36
#define BS_STRIDE 136
#define AS_FLOATS (128 * AS_STRIDE)          // 4608
#define BS_FLOATS (32 * BS_STRIDE)           // 4352
#define STAGE_FLOATS (AS_FLOATS + BS_FLOATS) // 8960
#define GEMM_SMEM (2 * STAGE_FLOATS * 4)     // 71680 B

__global__ __launch_bounds__(128, 2)
void gemm_mma(const float* __restrict__ A, const float* __restrict__ W,
              float* __restrict__ C, float* __restrict__ C2,
              const float* __restrict__ dis, int M, int K, int nChunk) {
    extern __shared__ float sm[];
    uint32_t smb;
    asm("{ .reg .u64 t; cvta.to.shared.u64 t, %1; cvt.u32.u64 %0, t; }"
        : "=r"(smb) : "l"(sm));

    const int tid  = threadIdx.x;
    const int lane = tid & 31;
    const int warp = tid >> 5;            // 0..3
    const int wm   = (warp & 1) * 64;
    const int wn   = (warp >> 1) * 64;
    const int grp  = lane >> 2;           // 0..7
    const int thr  = lane & 3;            // 0..3

    const int rowBase = blockIdx.y * 128;
    const int colBase = blockIdx.x * 128;

    // chunk loads: A 128x32 (1024 x16B), B 32x128 (1024 x16B); 16 per thread
    auto issue = [&](int chunk, int st) {
        const uint32_t base = smb + (uint32_t)st * (STAGE_FLOATS * 4);
        const int k0 = chunk * 32;
#pragma unroll
        for (int u = 0; u < 8; u++) {             // A
            int t = tid + u * 128;                // 0..1023
            int r = t >> 3, c = t & 7;
            uint32_t dst = base + (uint32_t)(r * AS_STRIDE + c * 4) * 4u;
            int row = rowBase + r;
            int ok  = row < M;
            const float* src = A + (size_t)(ok ? row : 0) * K + k0 + c * 4;
            CP_ASYNC16(dst, src, ok ? 16 : 0);
        }
#pragma unroll
        for (int u = 0; u < 8; u++) {             // B[k][n]
            int t = tid + u * 128;
            int kk = t >> 5, c = t & 31;
            uint32_t dst = base + (uint32_t)(AS_FLOATS + kk * BS_STRIDE + c * 4) * 4u;
            const float* src = W + (size_t)(k0 + kk) * NH + colBase + c * 4;
            CP_ASYNC16(dst, src, 16);
        }
    };

    float acc[4][8][4];
#pragma unroll
    for (int i = 0; i < 4; i++)
#pragma unroll
        for (int j = 0; j < 8; j++)
#pragma unroll
            for (int r = 0; r < 4; r++) acc[i][j][r] = 0.f;

    issue(0, 0);
    CP_COMMIT();

    for (int i = 0; i < nChunk; i++) {
        const int si = i & 1;
        if (i + 1 < nChunk) {
            issue(i + 1, si ^ 1);
            CP_COMMIT();
            CP_WAIT(1);
        } else {
            CP_WAIT(0);
        }
        __syncthreads();

        const float* As = sm + si * STAGE_FLOATS;
        const float* Bs = sm + si * STAGE_FLOATS + AS_FLOATS;

#pragma unroll
        for (int kk = 0; kk < 4; kk++) {
            const int kb = kk * 8;
            uint32_t af[4][4], bf[8][2];
#pragma unroll
            for (int mi = 0; mi < 4; mi++) {
                int m = wm + mi * 16 + grp;
                af[mi][0] = __float_as_uint(As[m * AS_STRIDE + kb + thr]);
                af[mi][1] = __float_as_uint(As[(m + 8) * AS_STRIDE + kb + thr]);
                af[mi][2] = __float_as_uint(As[m * AS_STRIDE + kb + 4 + thr]);
                af[mi][3] = __float_as_uint(As[(m + 8) * AS_STRIDE + kb + 4 + thr]);
            }
#pragma unroll
            for (int ni = 0; ni < 8; ni++) {
                int n = wn + ni * 8 + grp;
                bf[ni][0] = __float_as_uint(Bs[(kb + thr) * BS_STRIDE + n]);
                bf[ni][1] = __float_as_uint(Bs[(kb + 4 + thr) * BS_STRIDE + n]);
            }
#pragma unroll
            for (int mi = 0; mi < 4; mi++)
#pragma unroll
                for (int ni = 0; ni < 8; ni++)
                    mma_tf32(acc[mi][ni], af[mi], bf[ni]);
        }
        __syncthreads();
    }

    // epilogue: dual store (raw C, and C2 = C * dis^2)
#pragma unroll
    for (int mi = 0; mi < 4; mi++) {
        int m0 = rowBase + wm + mi * 16 + grp;
        int m1 = m0 + 8;
        float s0 = (m0 < M) ? dis[m0] * dis[m0] : 0.f;
        float s1 = (m1 < M) ? dis[m1] * dis[m1] : 0.f;
#pragma unroll
        for (int ni = 0; ni < 8; ni++) {
            int n0 = colBase + wn + ni * 8 + thr * 2;
            if (m0 < M) {
                *(float2*)&C [(size_t)m0 * NH + n0] = make_float2(acc[mi][ni][0], acc[mi][ni][1]);
                *(float2*)&C2[(size_t)m0 * NH + n0] = make_float2(acc[mi][ni][0] * s0, acc[mi][ni][1] * s0);
            }
            if (m1 < M) {
                *(float2*)&C [(size_t)m1 * NH + n0] = make_float2(acc[mi][ni][2], acc[mi][ni][3]);
                *(float2*)&C2[(size_t)m1 * NH + n0] = make_float2(acc[mi][ni][2] * s1, acc[mi][ni][3] * s1);
            }
        }
    }
}

// ---------------- weight prep ------------------------------------------------
__global__ void k_round_tf32(const float* __restrict__ W, float* __restrict__ Wr,
                             int total) {
    int i = blockIdx.x * blockDim.x + threadIdx.x;
    if (i < total) Wr[i] = to_tf32(W[i]);
}

// ---------------- degree / normalization ------------------------------------
__global__ void k_deg_init(float* deg) {
    int n = blockIdx.x * blockDim.x + threadIdx.x;
    if (n < NNODE) deg[n] = 1.0f;
}

__global__ void k_deg_count(const int* __restrict__ dst, float* deg) {
    int e = blockIdx.x * blockDim.x + threadIdx.x;
    if (e < NEDGE) atomicAdd(&deg[dst[e]], 1.0f);
}

__global__ void k_dis(const float* __restrict__ deg, float* dis) {
    int n = blockIdx.x * blockDim.x + threadIdx.x;
    if (n < NNODE) dis[n] = rsqrtf(deg[n]);
}

__global__ void k_norm(const int* __restrict__ src, const int* __restrict__ dst,
                       const float* __restrict__ dis, float* norm) {
    int e = blockIdx.x * blockDim.x + threadIdx.x;
    if (e < NEDGE) norm[e] = dis[src[e]] * dis[dst[e]];
}

// ---------------- message passing --------------------------------------------
__global__ __launch_bounds__(256)
void k_scatter(const float* __restrict__ in, float* __restrict__ out,
               const int* __restrict__ src, const int* __restrict__ dst,
               const float* __restrict__ norm) {
    int e = blockIdx.x;
    float w = norm[e];
    const float4* ip = (const float4*)(in + (size_t)src[e] * NH);
    float* op = out + (size_t)dst[e] * NH + threadIdx.x * 4;
    float4 v = ip[threadIdx.x];
    v.x *= w; v.y *= w; v.z *= w; v.w *= w;
    red_add_v4(op, v);
}

__global__ void k_bias_relu(float* __restrict__ x, const float* __restrict__ b) {
    size_t idx = (size_t)blockIdx.x * blockDim.x + threadIdx.x;
    if (idx >= (size_t)NNODE * (NH / 4)) return;
    int h = ((int)idx & (NH / 4 - 1)) * 4;
    float4 v = ((float4*)x)[idx];
    v.x = fmaxf(v.x + b[h + 0], 0.f);
    v.y = fmaxf(v.y + b[h + 1], 0.f);
    v.z = fmaxf(v.z + b[h + 2], 0.f);
    v.w = fmaxf(v.w + b[h + 3], 0.f);
    ((float4*)x)[idx] = v;
}

// ---------------- pooling (fused bias2 + relu) + head ------------------------
__global__ void k_zero_pool(float* pooled, float* cnt) {
    int i = blockIdx.x * blockDim.x + threadIdx.x;
    if (i < NG * NH) pooled[i] = 0.f;
    if (i < NG) cnt[i] = 0.f;
}

__global__ void k_count(const int* __restrict__ batch, float* cnt) {
    int n = blockIdx.x * blockDim.x + threadIdx.x;
    if (n < NNODE) atomicAdd(&cnt[batch[n]], 1.0f);
}

__global__ __launch_bounds__(256)
void k_pool(const float* __restrict__ a, const int* __restrict__ batch,
            const float* __restrict__ b, float* __restrict__ pooled) {
    int n = blockIdx.x;
    int g = batch[n];
    int h = threadIdx.x * 4;
    float4 v = ((const float4*)(a + (size_t)n * NH))[threadIdx.x];
    v.x = fmaxf(v.x + b[h + 0], 0.f);
    v.y = fmaxf(v.y + b[h + 1], 0.f);
    v.z = fmaxf(v.z + b[h + 2], 0.f);
    v.w = fmaxf(v.w + b[h + 3], 0.f);
    red_add_v4(pooled + (size_t)g * NH + h, v);
}

__global__ void k_comb(const float* __restrict__ gx, const float* __restrict__ pooled,
                       const float* __restrict__ cnt, float* __restrict__ comb) {
    int g = blockIdx.y;
    int i = blockIdx.x * blockDim.x + threadIdx.x;
    float v;
    if (i < NF) v = gx[(size_t)g * NF + i];
    else        v = pooled[(size_t)g * NH + (i - NF)] / fmaxf(cnt[g], 1.0f);
    comb[(size_t)g * NCOMB + i] = v;
}

__global__ __launch_bounds__(256)
void k_mlp1(const float* __restrict__ comb, const float* __restrict__ fw1,
            const float* __restrict__ fb1, float* __restrict__ hid) {
    __shared__ float sc[32][65];
    int j  = blockIdx.x * 16 + (threadIdx.x & 15);
    int gq = threadIdx.x >> 4;
    float acc[4] = {0.f, 0.f, 0.f, 0.f};
    for (int kb = 0; kb < NCOMB; kb += 32) {
#pragma unroll
        for (int u = 0; u < 8; u++) {
            int l = threadIdx.x + 256 * u;
            int g = l >> 5, kk = l & 31;
            sc[kk][g] = comb[(size_t)g * NCOMB + kb + kk];
        }
        __syncthreads();
#pragma unroll 8
        for (int kk = 0; kk < 32; kk++) {
            float w = fw1[(size_t)(kb + kk) * NFUSE + j];
#pragma unroll
            for (int q = 0; q < 4; q++) acc[q] += sc[kk][gq * 4 + q] * w;
        }
        __syncthreads();
    }
#pragma unroll
    for (int q = 0; q < 4; q++) {
        int g = gq * 4 + q;
        hid[(size_t)g * NFUSE + j] = fmaxf(acc[q] + fb1[j], 0.f);
    }
}

__global__ __launch_bounds__(128)
void k_mlp2(const float* __restrict__ hid, const float* __restrict__ fw2,
            const float* __restrict__ fb2, float* __restrict__ out) {
    __shared__ float sh[NFUSE];
    int g = blockIdx.x;
    for (int i = threadIdx.x; i < NFUSE; i += blockDim.x)
        sh[i] = hid[(size_t)g * NFUSE + i];
    __syncthreads();
    int c = threadIdx.x;
    if (c < NC) {
        float acc = 0.f;
#pragma unroll 4
        for (int k = 0; k < NFUSE; k++) acc += sh[k] * fw2[(size_t)k * NC + c];
        out[(size_t)g * NC + c] = acc + fb2[c];
    }
}

// ---------------- launch ------------------------------------------------------
extern "C" void kernel_launch(void* const* d_in, const int* in_sizes, int n_in,
                              void* d_out, int out_size) {
    const float* gx    = (const float*)d_in[0];
    const float* x     = (const float*)d_in[1];
    const int*   eidx  = (const int*)  d_in[2];
    const int*   batch = (const int*)  d_in[3];
    const float* W1    = (const float*)d_in[4];
    const float* b1    = (const float*)d_in[5];
    const float* W2    = (const float*)d_in[6];
    const float* b2    = (const float*)d_in[7];
    const float* fw1   = (const float*)d_in[8];
    const float* fb1   = (const float*)d_in[9];
    const float* fw2   = (const float*)d_in[10];
    const float* fb2   = (const float*)d_in[11];
    float* out = (float*)d_out;

    const int* src = eidx;
    const int* dst = eidx + NEDGE;

    float *buf1, *buf2, *buf3, *wt1, *wt2, *deg, *dis, *norm, *pooled, *cnt, *comb, *hid;
    cudaGetSymbolAddress((void**)&buf1,   g_buf1);
    cudaGetSymbolAddress((void**)&buf2,   g_buf2);
    cudaGetSymbolAddress((void**)&buf3,   g_buf3);
    cudaGetSymbolAddress((void**)&wt1,    g_wt1);
    cudaGetSymbolAddress((void**)&wt2,    g_wt2);
    cudaGetSymbolAddress((void**)&deg,    g_deg);
    cudaGetSymbolAddress((void**)&dis,    g_dis);
    cudaGetSymbolAddress((void**)&norm,   g_norm);
    cudaGetSymbolAddress((void**)&pooled, g_pooled);
    cudaGetSymbolAddress((void**)&cnt,    g_cnt);
    cudaGetSymbolAddress((void**)&comb,   g_comb);
    cudaGetSymbolAddress((void**)&hid,    g_hid);

    cudaFuncSetAttribute(gemm_mma, cudaFuncAttributeMaxDynamicSharedMemorySize,
                         GEMM_SMEM);

    const int TPB = 256;
    const int nodeBlocks = (NNODE + TPB - 1) / TPB;
    const int edgeBlocks = (NEDGE + TPB - 1) / TPB;
    const size_t vec4 = (size_t)NNODE * (NH / 4);
    const int vecBlocks = (int)((vec4 + TPB - 1) / TPB);

    dim3 gg(NH / 128, (NNODE + 127) / 128);   // (8, 391)

    // ordered so gemm_mma lands near ncu's -s 5 capture window
    k_deg_init  <<<nodeBlocks, TPB>>>(deg);                               // 1
    k_deg_count <<<edgeBlocks, TPB>>>(dst, deg);                          // 2
    k_dis       <<<nodeBlocks, TPB>>>(deg, dis);                          // 3
    k_round_tf32<<<(NF * NH + TPB - 1) / TPB, TPB>>>(W1, wt1, NF * NH);   // 4
    gemm_mma    <<<gg, 128, GEMM_SMEM>>>(x, wt1, buf1, buf2, dis,         // 5
                                         NNODE, NF, NF / 32);
    k_norm      <<<edgeBlocks, TPB>>>(src, dst, dis, norm);               // 6
    k_scatter   <<<NEDGE, 256>>>(buf1, buf2, src, dst, norm);             // 7
    k_bias_relu <<<vecBlocks, TPB>>>(buf2, b1);                           // 8

    k_round_tf32<<<(NH * NH + TPB - 1) / TPB, TPB>>>(W2, wt2, NH * NH);   // 9
    gemm_mma    <<<gg, 128, GEMM_SMEM>>>(buf2, wt2, buf1, buf3, dis,      // 10
                                         NNODE, NH, NH / 32);
    k_scatter   <<<NEDGE, 256>>>(buf1, buf3, src, dst, norm);             // 11

    k_zero_pool <<<(NG * NH + TPB - 1) / TPB, TPB>>>(pooled, cnt);        // 12
    k_count     <<<nodeBlocks, TPB>>>(batch, cnt);                        // 13
    k_pool      <<<NNODE, 256>>>(buf3, batch, b2, pooled);                // 14

    dim3 gc(NCOMB / TPB, NG);
    k_comb<<<gc, TPB>>>(gx, pooled, cnt, comb);                           // 15
    k_mlp1<<<NFUSE / 16, 256>>>(comb, fw1, fb1, hid);                     // 16
    k_mlp2<<<NG, 128>>>(hid, fw2, fb2, out);                              // 17
}

// round 6
// speedup vs baseline: 2.6595x; 1.0130x over previous
#include <cuda_runtime.h>
#include <cstdint>

#define NNODE 50000
#define NEDGE 200000
#define NG    64
#define NF    1536
#define NH    1024
#define NC    80
#define NFUSE 1024
#define NCOMB (NF + NH)   // 2560

// ---------------- scratch (device globals) ----------------------------------
__device__ float g_buf1[(size_t)NNODE * NH];
__device__ float g_buf2[(size_t)NNODE * NH];
__device__ float g_buf3[(size_t)NNODE * NH];
__device__ float g_wt1 [(size_t)NF * NH];      // W1 tf32-rounded [K,N]
__device__ float g_wt2 [(size_t)NH * NH];      // W2 tf32-rounded [K,N]
__device__ float g_deg [NNODE];
__device__ float g_dis [NNODE];
__device__ float g_norm[NEDGE];
__device__ float g_pooled[NG * NH];
__device__ float g_cnt [NG];
__device__ float g_comb[NG * NCOMB];
__device__ float g_hid [NG * NFUSE];

// ---------------- helpers ----------------------------------------------------
__device__ __forceinline__ float to_tf32(float x) {
    uint32_t u;
    asm("cvt.rna.tf32.f32 %0, %1;" : "=r"(u) : "f"(x));
    return __uint_as_float(u);
}

__device__ __forceinline__ void mma_tf32(float c[4], const uint32_t a[4],
                                         const uint32_t b[2]) {
    asm volatile(
        "mma.sync.aligned.m16n8k8.row.col.f32.tf32.tf32.f32 "
        "{%0,%1,%2,%3}, {%4,%5,%6,%7}, {%8,%9}, {%0,%1,%2,%3};"
        : "+f"(c[0]), "+f"(c[1]), "+f"(c[2]), "+f"(c[3])
        : "r"(a[0]), "r"(a[1]), "r"(a[2]), "r"(a[3]), "r"(b[0]), "r"(b[1]));
}

__device__ __forceinline__ void red_add_v4(float* p, float4 v) {
    asm volatile("red.add.v4.f32 [%0], {%1,%2,%3,%4};"
                 :: "l"(p), "f"(v.x), "f"(v.y), "f"(v.z), "f"(v.w) : "memory");
}

#define CP_ASYNC16(dst, src, sz) \
    asm volatile("cp.async.cg.shared.global [%0], [%1], 16, %2;" \
                 :: "r"(dst), "l"(src), "r"(sz) : "memory")
#define CP_COMMIT()  asm volatile("cp.async.commit_group;" ::: "memory")
#define CP_WAIT(n)   asm volatile("cp.async.wait_group %0;" :: "n"(n) : "memory")

// ---------------- tf32 mma.sync GEMM -----------------------------------------
// C[M,1024] = A[M,K] @ W[K,1024].  CTA tile 128x128, BK=32, 128 threads
// (4 warps 2m x 2n, warp tile 64x64 = 4x8 m16n8k8 frags), 3-stage cp.async,
// one __syncthreads per chunk, 2 CTAs/SM.
// Fused epilogue: C = result, C2 = result / deg[m]  (GCN self-loop init).
#define AS_STRIDE 36
#define BS_STRIDE 136
#define AS_FLOATS (128 * AS_STRIDE)          // 4608
#define BS_FLOATS (32 * BS_STRIDE)           // 4352
#define STAGE_FLOATS (AS_FLOATS + BS_FLOATS) // 8960
#define GEMM_SMEM (3 * STAGE_FLOATS * 4)     // 107520 B

__global__ __launch_bounds__(128, 2)
void gemm_mma(const float* __restrict__ A, const float* __restrict__ W,
              float* __restrict__ C, float* __restrict__ C2,
              const float* __restrict__ deg, int M, int K, int nChunk) {
    extern __shared__ float sm[];
    uint32_t smb;
    asm("{ .reg .u64 t; cvta.to.shared.u64 t, %1; cvt.u32.u64 %0, t; }"
        : "=r"(smb) : "l"(sm));

    const int tid  = threadIdx.x;
    const int lane = tid & 31;
    const int warp = tid >> 5;            // 0..3
    const int wm   = (warp & 1) * 64;
    const int wn   = (warp >> 1) * 64;
    const int grp  = lane >> 2;           // 0..7
    const int thr  = lane & 3;            // 0..3

    const int rowBase = blockIdx.y * 128;
    const int colBase = blockIdx.x * 128;

    auto issue = [&](int chunk, int st) {
        const uint32_t base = smb + (uint32_t)st * (STAGE_FLOATS * 4);
        const int k0 = chunk * 32;
#pragma unroll
        for (int u = 0; u < 8; u++) {             // A: 128 rows x 8 16B chunks
            int t = tid + u * 128;
            int r = t >> 3, c = t & 7;
            uint32_t dst = base + (uint32_t)(r * AS_STRIDE + c * 4) * 4u;
            int row = rowBase + r;
            int ok  = row < M;
            const float* src = A + (size_t)(ok ? row : 0) * K + k0 + c * 4;
            CP_ASYNC16(dst, src, ok ? 16 : 0);
        }
#pragma unroll
        for (int u = 0; u < 8; u++) {             // B[k][n]: 32 k x 32 16B chunks
            int t = tid + u * 128;
            int kk = t >> 5, c = t & 31;
            uint32_t dst = base + (uint32_t)(AS_FLOATS + kk * BS_STRIDE + c * 4) * 4u;
            const float* src = W + (size_t)(k0 + kk) * NH + colBase + c * 4;
            CP_ASYNC16(dst, src, 16);
        }
    };

    float acc[4][8][4];
#pragma unroll
    for (int i = 0; i < 4; i++)
#pragma unroll
        for (int j = 0; j < 8; j++)
#pragma unroll
            for (int r = 0; r < 4; r++) acc[i][j][r] = 0.f;

    issue(0, 0); CP_COMMIT();
    issue(1, 1); CP_COMMIT();

    for (int i = 0; i < nChunk; i++) {
        const int si = i % 3;
        CP_WAIT(1);                 // chunk i resident (<=1 newer group pending)
        __syncthreads();

        const float* As = sm + si * STAGE_FLOATS;
        const float* Bs = sm + si * STAGE_FLOATS + AS_FLOATS;

#pragma unroll
        for (int kk = 0; kk < 4; kk++) {
            const int kb = kk * 8;
            uint32_t af[4][4], bf[8][2];
#pragma unroll
            for (int mi = 0; mi < 4; mi++) {
                int m = wm + mi * 16 + grp;
                af[mi][0] = __float_as_uint(As[m * AS_STRIDE + kb + thr]);
                af[mi][1] = __float_as_uint(As[(m + 8) * AS_STRIDE + kb + thr]);
                af[mi][2] = __float_as_uint(As[m * AS_STRIDE + kb + 4 + thr]);
                af[mi][3] = __float_as_uint(As[(m + 8) * AS_STRIDE + kb + 4 + thr]);
            }
#pragma unroll
            for (int ni = 0; ni < 8; ni++) {
                int n = wn + ni * 8 + grp;
                bf[ni][0] = __float_as_uint(Bs[(kb + thr) * BS_STRIDE + n]);
                bf[ni][1] = __float_as_uint(Bs[(kb + 4 + thr) * BS_STRIDE + n]);
            }
#pragma unroll
            for (int mi = 0; mi < 4; mi++)
#pragma unroll
                for (int ni = 0; ni < 8; ni++)
                    mma_tf32(acc[mi][ni], af[mi], bf[ni]);
        }

        if (i + 2 < nChunk) { issue(i + 2, (i + 2) % 3); CP_COMMIT(); }
    }

    // epilogue: C = raw, C2 = raw / deg  (dis^2 == 1/deg, deg >= 1)
#pragma unroll
    for (int mi = 0; mi < 4; mi++) {
        int m0 = rowBase + wm + mi * 16 + grp;
        int m1 = m0 + 8;
        float s0 = (m0 < M) ? __frcp_rn(deg[m0]) : 0.f;
        float s1 = (m1 < M) ? __frcp_rn(deg[m1]) : 0.f;
#pragma unroll
        for (int ni = 0; ni < 8; ni++) {
            int n0 = colBase + wn + ni * 8 + thr * 2;
            if (m0 < M) {
                *(float2*)&C [(size_t)m0 * NH + n0] = make_float2(acc[mi][ni][0], acc[mi][ni][1]);
                *(float2*)&C2[(size_t)m0 * NH + n0] = make_float2(acc[mi][ni][0] * s0, acc[mi][ni][1] * s0);
            }
            if (m1 < M) {
                *(float2*)&C [(size_t)m1 * NH + n0] = make_float2(acc[mi][ni][2], acc[mi][ni][3]);
                *(float2*)&C2[(size_t)m1 * NH + n0] = make_float2(acc[mi][ni][2] * s1, acc[mi][ni][3] * s1);
            }
        }
    }
}

// ---------------- weight prep ------------------------------------------------
__global__ void k_round_tf32(const float* __restrict__ W, float* __restrict__ Wr,
                             int total) {
    int i = blockIdx.x * blockDim.x + threadIdx.x;
    if (i < total) Wr[i] = to_tf32(W[i]);
}

// ---------------- degree / normalization ------------------------------------
__global__ void k_deg_init(float* deg) {
    int n = blockIdx.x * blockDim.x + threadIdx.x;
    if (n < NNODE) deg[n] = 1.0f;
}

__global__ void k_deg_count(const int* __restrict__ dst, float* deg) {
    int e = blockIdx.x * blockDim.x + threadIdx.x;
    if (e < NEDGE) atomicAdd(&deg[dst[e]], 1.0f);
}

__global__ void k_dis(const float* __restrict__ deg, float* dis) {
    int n = blockIdx.x * blockDim.x + threadIdx.x;
    if (n < NNODE) dis[n] = rsqrtf(deg[n]);
}

__global__ void k_norm(const int* __restrict__ src, const int* __restrict__ dst,
                       const float* __restrict__ dis, float* norm) {
    int e = blockIdx.x * blockDim.x + threadIdx.x;
    if (e < NEDGE) norm[e] = dis[src[e]] * dis[dst[e]];
}

// ---------------- message passing --------------------------------------------
__global__ __launch_bounds__(256)
void k_scatter(const float* __restrict__ in, float* __restrict__ out,
               const int* __restrict__ src, const int* __restrict__ dst,
               const float* __restrict__ norm) {
    int e = blockIdx.x;
    float w = norm[e];
    const float4* ip = (const float4*)(in + (size_t)src[e] * NH);
    float* op = out + (size_t)dst[e] * NH + threadIdx.x * 4;
    float4 v = ip[threadIdx.x];
    v.x *= w; v.y *= w; v.z *= w; v.w *= w;
    red_add_v4(op, v);
}

__global__ void k_bias_relu(float* __restrict__ x, const float* __restrict__ b) {
    size_t idx = (size_t)blockIdx.x * blockDim.x + threadIdx.x;
    if (idx >= (size_t)NNODE * (NH / 4)) return;
    int h = ((int)idx & (NH / 4 - 1)) * 4;
    float4 v = ((float4*)x)[idx];
    v.x = fmaxf(v.x + b[h + 0], 0.f);
    v.y = fmaxf(v.y + b[h + 1], 0.f);
    v.z = fmaxf(v.z + b[h + 2], 0.f);
    v.w = fmaxf(v.w + b[h + 3], 0.f);
    ((float4*)x)[idx] = v;
}

// ---------------- pooling (fused bias2 + relu) + head ------------------------
__global__ void k_zero_pool(float* pooled, float* cnt) {
    int i = blockIdx.x * blockDim.x + threadIdx.x;
    if (i < NG * NH) pooled[i] = 0.f;
    if (i < NG) cnt[i] = 0.f;
}

__global__ void k_count(const int* __restrict__ batch, float* cnt) {
    int n = blockIdx.x * blockDim.x + threadIdx.x;
    if (n < NNODE) atomicAdd(&cnt[batch[n]], 1.0f);
}

__global__ __launch_bounds__(256)
void k_pool(const float* __restrict__ a, const int* __restrict__ batch,
            const float* __restrict__ b, float* __restrict__ pooled) {
    int n = blockIdx.x;
    int g = batch[n];
    int h = threadIdx.x * 4;
    float4 v = ((const float4*)(a + (size_t)n * NH))[threadIdx.x];
    v.x = fmaxf(v.x + b[h + 0], 0.f);
    v.y = fmaxf(v.y + b[h + 1], 0.f);
    v.z = fmaxf(v.z + b[h + 2], 0.f);
    v.w = fmaxf(v.w + b[h + 3], 0.f);
    red_add_v4(pooled + (size_t)g * NH + h, v);
}

__global__ void k_comb(const float* __restrict__ gx, const float* __restrict__ pooled,
                       const float* __restrict__ cnt, float* __restrict__ comb) {
    int g = blockIdx.y;
    int i = blockIdx.x * blockDim.x + threadIdx.x;
    float v;
    if (i < NF) v = gx[(size_t)g * NF + i];
    else        v = pooled[(size_t)g * NH + (i - NF)] / fmaxf(cnt[g], 1.0f);
    comb[(size_t)g * NCOMB + i] = v;
}

__global__ __launch_bounds__(256)
void k_mlp1(const float* __restrict__ comb, const float* __restrict__ fw1,
            const float* __restrict__ fb1, float* __restrict__ hid) {
    __shared__ float sc[32][65];
    int j  = blockIdx.x * 16 + (threadIdx.x & 15);
    int gq = threadIdx.x >> 4;
    float acc[4] = {0.f, 0.f, 0.f, 0.f};
    for (int kb = 0; kb < NCOMB; kb += 32) {
#pragma unroll
        for (int u = 0; u < 8; u++) {
            int l = threadIdx.x + 256 * u;
            int g = l >> 5, kk = l & 31;
            sc[kk][g] = comb[(size_t)g * NCOMB + kb + kk];
        }
        __syncthreads();
#pragma unroll 8
        for (int kk = 0; kk < 32; kk++) {
            float w = fw1[(size_t)(kb + kk) * NFUSE + j];
#pragma unroll
            for (int q = 0; q < 4; q++) acc[q] += sc[kk][gq * 4 + q] * w;
        }
        __syncthreads();
    }
#pragma unroll
    for (int q = 0; q < 4; q++) {
        int g = gq * 4 + q;
        hid[(size_t)g * NFUSE + j] = fmaxf(acc[q] + fb1[j], 0.f);
    }
}

__global__ __launch_bounds__(128)
void k_mlp2(const float* __restrict__ hid, const float* __restrict__ fw2,
            const float* __restrict__ fb2, float* __restrict__ out) {
    __shared__ float sh[NFUSE];
    int g = blockIdx.x;
    for (int i = threadIdx.x; i < NFUSE; i += blockDim.x)
        sh[i] = hid[(size_t)g * NFUSE + i];
    __syncthreads();
    int c = threadIdx.x;
    if (c < NC) {
        float acc = 0.f;
#pragma unroll 4
        for (int k = 0; k < NFUSE; k++) acc += sh[k] * fw2[(size_t)k * NC + c];
        out[(size_t)g * NC + c] = acc + fb2[c];
    }
}

// ---------------- launch ------------------------------------------------------
extern "C" void kernel_launch(void* const* d_in, const int* in_sizes, int n_in,
                              void* d_out, int out_size) {
    const float* gx    = (const float*)d_in[0];
    const float* x     = (const float*)d_in[1];
    const int*   eidx  = (const int*)  d_in[2];
    const int*   batch = (const int*)  d_in[3];
    const float* W1    = (const float*)d_in[4];
    const float* b1    = (const float*)d_in[5];
    const float* W2    = (const float*)d_in[6];
    const float* b2    = (const float*)d_in[7];
    const float* fw1   = (const float*)d_in[8];
    const float* fb1   = (const float*)d_in[9];
    const float* fw2   = (const float*)d_in[10];
    const float* fb2   = (const float*)d_in[11];
    float* out = (float*)d_out;

    const int* src = eidx;
    const int* dst = eidx + NEDGE;

    float *buf1, *buf2, *buf3, *wt1, *wt2, *deg, *dis, *norm, *pooled, *cnt, *comb, *hid;
    cudaGetSymbolAddress((void**)&buf1,   g_buf1);
    cudaGetSymbolAddress((void**)&buf2,   g_buf2);
    cudaGetSymbolAddress((void**)&buf3,   g_buf3);
    cudaGetSymbolAddress((void**)&wt1,    g_wt1);
    cudaGetSymbolAddress((void**)&wt2,    g_wt2);
    cudaGetSymbolAddress((void**)&deg,    g_deg);
    cudaGetSymbolAddress((void**)&dis,    g_dis);
    cudaGetSymbolAddress((void**)&norm,   g_norm);
    cudaGetSymbolAddress((void**)&pooled, g_pooled);
    cudaGetSymbolAddress((void**)&cnt,    g_cnt);
    cudaGetSymbolAddress((void**)&comb,   g_comb);
    cudaGetSymbolAddress((void**)&hid,    g_hid);

    cudaFuncSetAttribute(gemm_mma, cudaFuncAttributeMaxDynamicSharedMemorySize,
                         GEMM_SMEM);

    const int TPB = 256;
    const int nodeBlocks = (NNODE + TPB - 1) / TPB;
    const int edgeBlocks = (NEDGE + TPB - 1) / TPB;
    const size_t vec4 = (size_t)NNODE * (NH / 4);
    const int vecBlocks = (int)((vec4 + TPB - 1) / TPB);

    dim3 gg(NH / 128, (NNODE + 127) / 128);   // (8, 391)

    // gemm at launch #4 (the slot ncu captured in R4/R5)
    k_round_tf32<<<(NF * NH + TPB - 1) / TPB, TPB>>>(W1, wt1, NF * NH);   // 1
    k_deg_init  <<<nodeBlocks, TPB>>>(deg);                               // 2
    k_deg_count <<<edgeBlocks, TPB>>>(dst, deg);                          // 3
    gemm_mma    <<<gg, 128, GEMM_SMEM>>>(x, wt1, buf1, buf2, deg,         // 4
                                         NNODE, NF, NF / 32);
    k_dis       <<<nodeBlocks, TPB>>>(deg, dis);                          // 5
    k_norm      <<<edgeBlocks, TPB>>>(src, dst, dis, norm);               // 6
    k_scatter   <<<NEDGE, 256>>>(buf1, buf2, src, dst, norm);             // 7
    k_bias_relu <<<vecBlocks, TPB>>>(buf2, b1);                           // 8

    k_round_tf32<<<(NH * NH + TPB - 1) / TPB, TPB>>>(W2, wt2, NH * NH);   // 9
    gemm_mma    <<<gg, 128, GEMM_SMEM>>>(buf2, wt2, buf1, buf3, deg,      // 10
                                         NNODE, NH, NH / 32);
    k_scatter   <<<NEDGE, 256>>>(buf1, buf3, src, dst, norm);             // 11

    k_zero_pool <<<(NG * NH + TPB - 1) / TPB, TPB>>>(pooled, cnt);        // 12
    k_count     <<<nodeBlocks, TPB>>>(batch, cnt);                        // 13
    k_pool      <<<NNODE, 256>>>(buf3, batch, b2, pooled);                // 14

    dim3 gc(NCOMB / TPB, NG);
    k_comb<<<gc, TPB>>>(gx, pooled, cnt, comb);                           // 15
    k_mlp1<<<NFUSE / 16, 256>>>(comb, fw1, fb1, hid);                     // 16
    k_mlp2<<<NG, 128>>>(hid, fw2, fb2, out);                              // 17
}

// round 7
// speedup vs baseline: 3.4068x; 1.2810x over previous
#include <cuda_runtime.h>
#include <cstdint>

#define NNODE 50000
#define NEDGE 200000
#define NG    64
#define NF    1536
#define NH    1024
#define NC    80
#define NFUSE 1024
#define NCOMB (NF + NH)   // 2560
#define NSCANB 196        // ceil(NNODE/256)

// ---------------- scratch (device globals) ----------------------------------
__device__ float g_buf1[(size_t)NNODE * NH];
__device__ float g_buf2[(size_t)NNODE * NH];
__device__ float g_wt1 [(size_t)NF * NH];
__device__ float g_wt2 [(size_t)NH * NH];
__device__ float g_dis  [NNODE];
__device__ float g_selfw[NNODE];
__device__ int   g_cnti [NNODE];
__device__ int   g_cur  [NNODE];
__device__ int   g_basev[NNODE + 1];
__device__ int   g_bsum [256];
__device__ int   g_csrs [NEDGE];
__device__ float g_csrw [NEDGE];
__device__ float g_pooled[NG * NH];
__device__ float g_cntg [NG];
__device__ float g_comb[NG * NCOMB];
__device__ float g_hid [NG * NFUSE];

// ---------------- helpers ----------------------------------------------------
__device__ __forceinline__ float to_tf32(float x) {
    uint32_t u;
    asm("cvt.rna.tf32.f32 %0, %1;" : "=r"(u) : "f"(x));
    return __uint_as_float(u);
}

__device__ __forceinline__ void mma_tf32(float c[4], const uint32_t a[4],
                                         const uint32_t b[2]) {
    asm volatile(
        "mma.sync.aligned.m16n8k8.row.col.f32.tf32.tf32.f32 "
        "{%0,%1,%2,%3}, {%4,%5,%6,%7}, {%8,%9}, {%0,%1,%2,%3};"
        : "+f"(c[0]), "+f"(c[1]), "+f"(c[2]), "+f"(c[3])
        : "r"(a[0]), "r"(a[1]), "r"(a[2]), "r"(a[3]), "r"(b[0]), "r"(b[1]));
}

__device__ __forceinline__ void red_add_v4(float* p, float4 v) {
    asm volatile("red.add.v4.f32 [%0], {%1,%2,%3,%4};"
                 :: "l"(p), "f"(v.x), "f"(v.y), "f"(v.z), "f"(v.w) : "memory");
}

#define CP_ASYNC16(dst, src, sz) \
    asm volatile("cp.async.cg.shared.global [%0], [%1], 16, %2;" \
                 :: "r"(dst), "l"(src), "r"(sz) : "memory")
#define CP_COMMIT()  asm volatile("cp.async.commit_group;" ::: "memory")
#define CP_WAIT(n)   asm volatile("cp.async.wait_group %0;" :: "n"(n) : "memory")

// ---------------- tf32 mma.sync GEMM (single-output epilogue) ----------------
#define AS_STRIDE 36
#define BS_STRIDE 136
#define AS_FLOATS (128 * AS_STRIDE)
#define BS_FLOATS (32 * BS_STRIDE)
#define STAGE_FLOATS (AS_FLOATS + BS_FLOATS)
#define GEMM_SMEM (3 * STAGE_FLOATS * 4)     // 107520 B

__global__ __launch_bounds__(128, 2)
void gemm_mma(const float* __restrict__ A, const float* __restrict__ W,
              float* __restrict__ C, int M, int K, int nChunk) {
    extern __shared__ float sm[];
    uint32_t smb;
    asm("{ .reg .u64 t; cvta.to.shared.u64 t, %1; cvt.u32.u64 %0, t; }"
        : "=r"(smb) : "l"(sm));

    const int tid  = threadIdx.x;
    const int lane = tid & 31;
    const int warp = tid >> 5;
    const int wm   = (warp & 1) * 64;
    const int wn   = (warp >> 1) * 64;
    const int grp  = lane >> 2;
    const int thr  = lane & 3;

    const int rowBase = blockIdx.y * 128;
    const int colBase = blockIdx.x * 128;

    auto issue = [&](int chunk, int st) {
        const uint32_t base = smb + (uint32_t)st * (STAGE_FLOATS * 4);
        const int k0 = chunk * 32;
#pragma unroll
        for (int u = 0; u < 8; u++) {
            int t = tid + u * 128;
            int r = t >> 3, c = t & 7;
            uint32_t dst = base + (uint32_t)(r * AS_STRIDE + c * 4) * 4u;
            int row = rowBase + r;
            int ok  = row < M;
            const float* src = A + (size_t)(ok ? row : 0) * K + k0 + c * 4;
            CP_ASYNC16(dst, src, ok ? 16 : 0);
        }
#pragma unroll
        for (int u = 0; u < 8; u++) {
            int t = tid + u * 128;
            int kk = t >> 5, c = t & 31;
            uint32_t dst = base + (uint32_t)(AS_FLOATS + kk * BS_STRIDE + c * 4) * 4u;
            const float* src = W + (size_t)(k0 + kk) * NH + colBase + c * 4;
            CP_ASYNC16(dst, src, 16);
        }
    };

    float acc[4][8][4];
#pragma unroll
    for (int i = 0; i < 4; i++)
#pragma unroll
        for (int j = 0; j < 8; j++)
#pragma unroll
            for (int r = 0; r < 4; r++) acc[i][j][r] = 0.f;

    issue(0, 0); CP_COMMIT();
    issue(1, 1); CP_COMMIT();

    for (int i = 0; i < nChunk; i++) {
        const int si = i % 3;
        CP_WAIT(1);
        __syncthreads();

        const float* As = sm + si * STAGE_FLOATS;
        const float* Bs = sm + si * STAGE_FLOATS + AS_FLOATS;

#pragma unroll
        for (int kk = 0; kk < 4; kk++) {
            const int kb = kk * 8;
            uint32_t af[4][4], bf[8][2];
#pragma unroll
            for (int mi = 0; mi < 4; mi++) {
                int m = wm + mi * 16 + grp;
                af[mi][0] = __float_as_uint(As[m * AS_STRIDE + kb + thr]);
                af[mi][1] = __float_as_uint(As[(m + 8) * AS_STRIDE + kb + thr]);
                af[mi][2] = __float_as_uint(As[m * AS_STRIDE + kb + 4 + thr]);
                af[mi][3] = __float_as_uint(As[(m + 8) * AS_STRIDE + kb + 4 + thr]);
            }
#pragma unroll
            for (int ni = 0; ni < 8; ni++) {
                int n = wn + ni * 8 + grp;
                bf[ni][0] = __float_as_uint(Bs[(kb + thr) * BS_STRIDE + n]);
                bf[ni][1] = __float_as_uint(Bs[(kb + 4 + thr) * BS_STRIDE + n]);
            }
#pragma unroll
            for (int mi = 0; mi < 4; mi++)
#pragma unroll
                for (int ni = 0; ni < 8; ni++)
                    mma_tf32(acc[mi][ni], af[mi], bf[ni]);
        }

        if (i + 2 < nChunk) { issue(i + 2, (i + 2) % 3); CP_COMMIT(); }
    }

#pragma unroll
    for (int mi = 0; mi < 4; mi++) {
        int m0 = rowBase + wm + mi * 16 + grp;
        int m1 = m0 + 8;
#pragma unroll
        for (int ni = 0; ni < 8; ni++) {
            int n0 = colBase + wn + ni * 8 + thr * 2;
            if (m0 < M)
                *(float2*)&C[(size_t)m0 * NH + n0] = make_float2(acc[mi][ni][0], acc[mi][ni][1]);
            if (m1 < M)
                *(float2*)&C[(size_t)m1 * NH + n0] = make_float2(acc[mi][ni][2], acc[mi][ni][3]);
        }
    }
}

// ---------------- weight prep -------------------------------------------------
__global__ void k_round_tf32(const float* __restrict__ W, float* __restrict__ Wr,
                             int total) {
    int i = blockIdx.x * blockDim.x + threadIdx.x;
    if (i < total) Wr[i] = to_tf32(W[i]);
}

// ---------------- CSR build ----------------------------------------------------
__global__ void k_zero_all(int* cnti, int* cur, float* pooled, float* cntg) {
    int i = blockIdx.x * blockDim.x + threadIdx.x;
    if (i < NNODE) { cnti[i] = 0; cur[i] = 0; }
    if (i < NG * NH) pooled[i] = 0.f;
    if (i < NG) cntg[i] = 0.f;
}

__global__ void k_count_i(const int* __restrict__ dst, int* cnti) {
    int e = blockIdx.x * blockDim.x + threadIdx.x;
    if (e < NEDGE) atomicAdd(&cnti[dst[e]], 1);
}

// dis = rsqrt(1+cnt), selfw = 1/(1+cnt)
__global__ void k_dis(const int* __restrict__ cnti, float* dis, float* selfw) {
    int n = blockIdx.x * blockDim.x + threadIdx.x;
    if (n < NNODE) {
        float d = 1.0f + (float)cnti[n];
        dis[n]   = rsqrtf(d);
        selfw[n] = 1.0f / d;
    }
}

// pass 1: per-256-block exclusive scan + block totals
__global__ __launch_bounds__(256)
void k_scan1(const int* __restrict__ cnti, int* base, int* bsum) {
    __shared__ int s[256];
    int n = blockIdx.x * 256 + threadIdx.x;
    int v = (n < NNODE) ? cnti[n] : 0;
    s[threadIdx.x] = v;
    __syncthreads();
#pragma unroll
    for (int o = 1; o < 256; o <<= 1) {
        int t = (threadIdx.x >= o) ? s[threadIdx.x - o] : 0;
        __syncthreads();
        s[threadIdx.x] += t;
        __syncthreads();
    }
    if (n < NNODE) base[n] = s[threadIdx.x] - v;   // exclusive within block
    if (threadIdx.x == 255) bsum[blockIdx.x] = s[255];
}

// pass 2: exclusive scan of block sums (NSCANB <= 256)
__global__ __launch_bounds__(256)
void k_scan2(int* bsum) {
    __shared__ int s[256];
    int v = (threadIdx.x < NSCANB) ? bsum[threadIdx.x] : 0;
    s[threadIdx.x] = v;
    __syncthreads();
#pragma unroll
    for (int o = 1; o < 256; o <<= 1) {
        int t = (threadIdx.x >= o) ? s[threadIdx.x - o] : 0;
        __syncthreads();
        s[threadIdx.x] += t;
        __syncthreads();
    }
    if (threadIdx.x < NSCANB) bsum[threadIdx.x] = s[threadIdx.x] - v;
}

// pass 3: add block offsets
__global__ void k_scan3(int* base, const int* __restrict__ bsum) {
    int n = blockIdx.x * 256 + threadIdx.x;
    if (n < NNODE) base[n] += bsum[blockIdx.x];
    if (n == 0) base[NNODE] = NEDGE;
}

__global__ void k_fill(const int* __restrict__ src, const int* __restrict__ dst,
                       const float* __restrict__ dis, const int* __restrict__ base,
                       int* cur, int* csrs, float* csrw) {
    int e = blockIdx.x * blockDim.x + threadIdx.x;
    if (e < NEDGE) {
        int d = dst[e], s = src[e];
        int pos = base[d] + atomicAdd(&cur[d], 1);
        csrs[pos] = s;
        csrw[pos] = dis[s] * dis[d];
    }
}

// ---------------- gather (CSR) message passing --------------------------------
// out[n] = relu( bias + selfw[n]*in[n] + sum_e w_e * in[src_e] )
__global__ __launch_bounds__(256)
void k_gather_relu(const float* __restrict__ in, float* __restrict__ out,
                   const int* __restrict__ csrs, const float* __restrict__ csrw,
                   const int* __restrict__ base, const float* __restrict__ selfw,
                   const float* __restrict__ bias) {
    int n = blockIdx.x;
    int t = threadIdx.x;
    int b0 = base[n], b1 = base[n + 1];
    float s = selfw[n];
    float4 v = ((const float4*)(in + (size_t)n * NH))[t];
    float4 acc = make_float4(v.x * s, v.y * s, v.z * s, v.w * s);
    for (int j = b0; j < b1; j++) {
        int sn  = csrs[j];
        float w = csrw[j];
        float4 u = ((const float4*)(in + (size_t)sn * NH))[t];
        acc.x += u.x * w; acc.y += u.y * w; acc.z += u.z * w; acc.w += u.w * w;
    }
    int h = t * 4;
    acc.x = fmaxf(acc.x + bias[h + 0], 0.f);
    acc.y = fmaxf(acc.y + bias[h + 1], 0.f);
    acc.z = fmaxf(acc.z + bias[h + 2], 0.f);
    acc.w = fmaxf(acc.w + bias[h + 3], 0.f);
    ((float4*)(out + (size_t)n * NH))[t] = acc;
}

// same, but reduce into pooled[batch[n]] instead of writing the row
__global__ __launch_bounds__(256)
void k_gather_pool(const float* __restrict__ in, const int* __restrict__ batch,
                   const int* __restrict__ csrs, const float* __restrict__ csrw,
                   const int* __restrict__ base, const float* __restrict__ selfw,
                   const float* __restrict__ bias, float* __restrict__ pooled,
                   float* __restrict__ cntg) {
    int n = blockIdx.x;
    int t = threadIdx.x;
    int b0 = base[n], b1 = base[n + 1];
    float s = selfw[n];
    float4 v = ((const float4*)(in + (size_t)n * NH))[t];
    float4 acc = make_float4(v.x * s, v.y * s, v.z * s, v.w * s);
    for (int j = b0; j < b1; j++) {
        int sn  = csrs[j];
        float w = csrw[j];
        float4 u = ((const float4*)(in + (size_t)sn * NH))[t];
        acc.x += u.x * w; acc.y += u.y * w; acc.z += u.z * w; acc.w += u.w * w;
    }
    int h = t * 4;
    acc.x = fmaxf(acc.x + bias[h + 0], 0.f);
    acc.y = fmaxf(acc.y + bias[h + 1], 0.f);
    acc.z = fmaxf(acc.z + bias[h + 2], 0.f);
    acc.w = fmaxf(acc.w + bias[h + 3], 0.f);
    int g = batch[n];
    red_add_v4(pooled + (size_t)g * NH + h, acc);
    if (t == 0) atomicAdd(&cntg[g], 1.0f);
}

// ---------------- head ---------------------------------------------------------
__global__ void k_comb(const float* __restrict__ gx, const float* __restrict__ pooled,
                       const float* __restrict__ cntg, float* __restrict__ comb) {
    int g = blockIdx.y;
    int i = blockIdx.x * blockDim.x + threadIdx.x;
    float v;
    if (i < NF) v = gx[(size_t)g * NF + i];
    else        v = pooled[(size_t)g * NH + (i - NF)] / fmaxf(cntg[g], 1.0f);
    comb[(size_t)g * NCOMB + i] = v;
}

__global__ __launch_bounds__(256)
void k_mlp1(const float* __restrict__ comb, const float* __restrict__ fw1,
            const float* __restrict__ fb1, float* __restrict__ hid) {
    __shared__ float sc[32][65];
    int j  = blockIdx.x * 16 + (threadIdx.x & 15);
    int gq = threadIdx.x >> 4;
    float acc[4] = {0.f, 0.f, 0.f, 0.f};
    for (int kb = 0; kb < NCOMB; kb += 32) {
#pragma unroll
        for (int u = 0; u < 8; u++) {
            int l = threadIdx.x + 256 * u;
            int g = l >> 5, kk = l & 31;
            sc[kk][g] = comb[(size_t)g * NCOMB + kb + kk];
        }
        __syncthreads();
#pragma unroll 8
        for (int kk = 0; kk < 32; kk++) {
            float w = fw1[(size_t)(kb + kk) * NFUSE + j];
#pragma unroll
            for (int q = 0; q < 4; q++) acc[q] += sc[kk][gq * 4 + q] * w;
        }
        __syncthreads();
    }
#pragma unroll
    for (int q = 0; q < 4; q++) {
        int g = gq * 4 + q;
        hid[(size_t)g * NFUSE + j] = fmaxf(acc[q] + fb1[j], 0.f);
    }
}

__global__ __launch_bounds__(128)
void k_mlp2(const float* __restrict__ hid, const float* __restrict__ fw2,
            const float* __restrict__ fb2, float* __restrict__ out) {
    __shared__ float sh[NFUSE];
    int g = blockIdx.x;
    for (int i = threadIdx.x; i < NFUSE; i += blockDim.x)
        sh[i] = hid[(size_t)g * NFUSE + i];
    __syncthreads();
    int c = threadIdx.x;
    if (c < NC) {
        float acc = 0.f;
#pragma unroll 4
        for (int k = 0; k < NFUSE; k++) acc += sh[k] * fw2[(size_t)k * NC + c];
        out[(size_t)g * NC + c] = acc + fb2[c];
    }
}

// ---------------- launch --------------------------------------------------------
extern "C" void kernel_launch(void* const* d_in, const int* in_sizes, int n_in,
                              void* d_out, int out_size) {
    const float* gx    = (const float*)d_in[0];
    const float* x     = (const float*)d_in[1];
    const int*   eidx  = (const int*)  d_in[2];
    const int*   batch = (const int*)  d_in[3];
    const float* W1    = (const float*)d_in[4];
    const float* b1    = (const float*)d_in[5];
    const float* W2    = (const float*)d_in[6];
    const float* b2    = (const float*)d_in[7];
    const float* fw1   = (const float*)d_in[8];
    const float* fb1   = (const float*)d_in[9];
    const float* fw2   = (const float*)d_in[10];
    const float* fb2   = (const float*)d_in[11];
    float* out = (float*)d_out;

    const int* src = eidx;
    const int* dst = eidx + NEDGE;

    float *buf1, *buf2, *wt1, *wt2, *dis, *selfw, *csrw, *pooled, *cntg, *comb, *hid;
    int *cnti, *cur, *basev, *bsum, *csrs;
    cudaGetSymbolAddress((void**)&buf1,   g_buf1);
    cudaGetSymbolAddress((void**)&buf2,   g_buf2);
    cudaGetSymbolAddress((void**)&wt1,    g_wt1);
    cudaGetSymbolAddress((void**)&wt2,    g_wt2);
    cudaGetSymbolAddress((void**)&dis,    g_dis);
    cudaGetSymbolAddress((void**)&selfw,  g_selfw);
    cudaGetSymbolAddress((void**)&cnti,   g_cnti);
    cudaGetSymbolAddress((void**)&cur,    g_cur);
    cudaGetSymbolAddress((void**)&basev,  g_basev);
    cudaGetSymbolAddress((void**)&bsum,   g_bsum);
    cudaGetSymbolAddress((void**)&csrs,   g_csrs);
    cudaGetSymbolAddress((void**)&csrw,   g_csrw);
    cudaGetSymbolAddress((void**)&pooled, g_pooled);
    cudaGetSymbolAddress((void**)&cntg,   g_cntg);
    cudaGetSymbolAddress((void**)&comb,   g_comb);
    cudaGetSymbolAddress((void**)&hid,    g_hid);

    cudaFuncSetAttribute(gemm_mma, cudaFuncAttributeMaxDynamicSharedMemorySize,
                         GEMM_SMEM);

    const int TPB = 256;
    const int edgeBlocks = (NEDGE + TPB - 1) / TPB;
    const int zeroBlocks = (NG * NH + TPB - 1) / TPB;   // covers NNODE too? no:
    const int zb = ((NNODE > NG * NH ? NNODE : NG * NH) + TPB - 1) / TPB;
    (void)zeroBlocks;

    dim3 gg(NH / 128, (NNODE + 127) / 128);   // (8, 391)

    // gemm at launch slot 4 (ncu capture window)
    k_round_tf32<<<(NF * NH + TPB - 1) / TPB, TPB>>>(W1, wt1, NF * NH);     // 1
    k_zero_all  <<<zb, TPB>>>(cnti, cur, pooled, cntg);                     // 2
    k_count_i   <<<edgeBlocks, TPB>>>(dst, cnti);                           // 3
    gemm_mma    <<<gg, 128, GEMM_SMEM>>>(x, wt1, buf1, NNODE, NF, NF / 32); // 4
    k_dis       <<<NSCANB, TPB>>>(cnti, dis, selfw);                        // 5
    k_scan1     <<<NSCANB, TPB>>>(cnti, basev, bsum);                       // 6
    k_scan2     <<<1, TPB>>>(bsum);                                         // 7
    k_scan3     <<<NSCANB, TPB>>>(basev, bsum);                             // 8
    k_fill      <<<edgeBlocks, TPB>>>(src, dst, dis, basev, cur, csrs, csrw); // 9
    k_gather_relu<<<NNODE, 256>>>(buf1, buf2, csrs, csrw, basev, selfw, b1);  // 10

    k_round_tf32<<<(NH * NH + TPB - 1) / TPB, TPB>>>(W2, wt2, NH * NH);     // 11
    gemm_mma    <<<gg, 128, GEMM_SMEM>>>(buf2, wt2, buf1, NNODE, NH, NH / 32); // 12
    k_gather_pool<<<NNODE, 256>>>(buf1, batch, csrs, csrw, basev, selfw, b2,
                                  pooled, cntg);                            // 13

    dim3 gc(NCOMB / TPB, NG);
    k_comb<<<gc, TPB>>>(gx, pooled, cntg, comb);                            // 14
    k_mlp1<<<NFUSE / 16, 256>>>(comb, fw1, fb1, hid);                       // 15
    k_mlp2<<<NG, 128>>>(hid, fw2, fb2, out);                                // 16
}